// round 12
// baseline (speedup 1.0000x reference)
#include <cuda_runtime.h>
#include <cuda_bf16.h>
#include <math.h>
#include <stdint.h>

#define NN 50000
#define NE 800000
#define EPS 1e-5f
#define AST 72

// ---------- static scratch ----------
__device__ __align__(16) float g_V2[NN*64];
__device__ __align__(16) float g_V3[NN*64];
__device__ __align__(16) float g_aggSA[NN*64];
__device__ __align__(16) float g_aggMA[NN*64];
__device__ __align__(16) float g_aggSB[NN*64];
__device__ __align__(16) float g_aggMB[NN*64];
__device__ __align__(16) float g_YvA[(size_t)NN*192];
__device__ __align__(16) float g_YvB[(size_t)NN*192];
__device__ __align__(16) float g_E2[(size_t)NE*64];
__device__ __align__(16) float g_E3[(size_t)NE*64];
__device__ __align__(16) float g_YeA[(size_t)NE*192];
__device__ __align__(16) float g_YeB[(size_t)NE*192];
__device__ __align__(16) float g_Yfv[(size_t)NN*128];
__device__ __align__(16) float g_Yfe[(size_t)NE*128];
__device__ int   g_deg[NN];
__device__ int   g_rowptr[NN+1];
__device__ int   g_cursor[NN];
__device__ int   g_perm[NE];
__device__ int   g_srcPerm[NE];
__device__ __align__(16) float g_softp[8][3];
__device__ __align__(16) float g_stats[10][2][192];
__device__ __align__(16) float g_scale[8][192];
__device__ __align__(16) float g_shift[8][192];
__device__ __align__(16) float g_fmean[2][128];
__device__ __align__(16) float g_finv[2][128];

__device__ __forceinline__ float leakyf(float x){ return x > 0.f ? x : 0.2f*x; }

// ---------- mma.sync helpers (LDS.32 fragment loads — proven round-8 path) ----------
static __device__ __forceinline__ void mma_bf16(float* d, const uint32_t* a, const uint32_t* b){
    asm volatile("mma.sync.aligned.m16n8k16.row.col.f32.bf16.bf16.f32 "
        "{%0,%1,%2,%3}, {%4,%5,%6,%7}, {%8,%9}, {%0,%1,%2,%3};"
        : "+f"(d[0]),"+f"(d[1]),"+f"(d[2]),"+f"(d[3])
        : "r"(a[0]),"r"(a[1]),"r"(a[2]),"r"(a[3]),"r"(b[0]),"r"(b[1]));
}
static __device__ __forceinline__ void ldA(uint32_t* a, const unsigned char* base, int mrow, int k0, int lane){
    int g = lane>>2, t2 = (lane&3)*2;
    const unsigned char* p = base + (size_t)((mrow+g)*AST + k0 + t2)*2;
    a[0] = *(const uint32_t*)p;
    a[2] = *(const uint32_t*)(p + 16);
    const unsigned char* q = p + 8*AST*2;
    a[1] = *(const uint32_t*)q;
    a[3] = *(const uint32_t*)(q + 16);
}
static __device__ __forceinline__ void ldB(uint32_t* b, const unsigned char* base, int n0, int k0, int lane){
    int g = lane>>2, t2 = (lane&3)*2;
    const unsigned char* p = base + (size_t)((n0+g)*AST + k0 + t2)*2;
    b[0] = *(const uint32_t*)p;
    b[1] = *(const uint32_t*)(p + 16);
}
static __device__ __forceinline__ void st2(unsigned char* H, unsigned char* L, int row, int col, float v0, float v1){
    uint32_t off = (uint32_t)(row*AST + col)*2;
    __nv_bfloat16 h0=__float2bfloat16(v0), h1=__float2bfloat16(v1);
    __nv_bfloat16 l0=__float2bfloat16(v0-__bfloat162float(h0));
    __nv_bfloat16 l1=__float2bfloat16(v1-__bfloat162float(h1));
    __nv_bfloat162 th; th.x=h0; th.y=h1;
    __nv_bfloat162 tl; tl.x=l0; tl.y=l1;
    *(__nv_bfloat162*)(H+off)=th;
    *(__nv_bfloat162*)(L+off)=tl;
}
static __device__ __forceinline__ void wsplit(float w, __nv_bfloat16* h, __nv_bfloat16* l){
    *h = __float2bfloat16(w);
    *l = __float2bfloat16(w - __bfloat162float(*h));
}

// ---------- setup ----------
__global__ void k_prep(const float* __restrict__ arch){
    int idx = blockIdx.x*blockDim.x + threadIdx.x;
    if (idx < NN) g_deg[idx] = 0;
    if (idx < 10*2*192) (&g_stats[0][0][0])[idx] = 0.f;
    if (idx < 8){
        float a0=arch[idx*3+0], a1=arch[idx*3+1], a2=arch[idx*3+2];
        float mx=fmaxf(a0,fmaxf(a1,a2));
        float e0=__expf(a0-mx), e1=__expf(a1-mx), e2=__expf(a2-mx);
        float s=e0+e1+e2;
        g_softp[idx][0]=e0/s; g_softp[idx][1]=e1/s; g_softp[idx][2]=e2/s;
    }
}
__global__ void k_count(const int* __restrict__ dst){
    int e = blockIdx.x*blockDim.x + threadIdx.x;
    if (e < NE) atomicAdd(&g_deg[dst[e]], 1);
}
__global__ void k_scan(){
    __shared__ int part[1024];
    int tid = threadIdx.x;
    const int CH = (NN + 1023)/1024;
    int base = tid*CH, s = 0;
    for (int i = 0; i < CH; i++){ int ix = base+i; if (ix < NN) s += g_deg[ix]; }
    part[tid] = s; __syncthreads();
    for (int off = 1; off < 1024; off <<= 1){
        int v = part[tid];
        int add = (tid >= off) ? part[tid-off] : 0;
        __syncthreads(); part[tid] = v + add; __syncthreads();
    }
    int run = (tid == 0) ? 0 : part[tid-1];
    for (int i = 0; i < CH; i++){
        int ix = base+i;
        if (ix < NN){ g_rowptr[ix]=run; g_cursor[ix]=run; run += g_deg[ix]; }
    }
    if (tid == 1023) g_rowptr[NN] = part[1023];
}
__global__ void k_scatter(const int* __restrict__ src, const int* __restrict__ dst){
    int e = blockIdx.x*blockDim.x + threadIdx.x;
    if (e < NE){
        int d = dst[e];
        int pos = atomicAdd(&g_cursor[d], 1);
        g_perm[pos] = e;
        g_srcPerm[pos] = src[e];
    }
}

// ---------- aggregation ----------
__global__ void __launch_bounds__(256)
k_agg(const float* __restrict__ Es, const float* __restrict__ V,
      float* __restrict__ aggS, float* __restrict__ aggM)
{
    int warp = (blockIdx.x*blockDim.x + threadIdx.x) >> 5;
    int lane = threadIdx.x & 31;
    if (warp >= NN) return;
    int beg = g_rowptr[warp], end = g_rowptr[warp+1];
    float s0=0.f, s1=0.f, m0=-INFINITY, m1=-INFINITY;
    for (int i = beg; i < end; i++){
        int e = g_perm[i], s = g_srcPerm[i];
        float2 ev = *reinterpret_cast<const float2*>(Es + (size_t)e*64 + lane*2);
        float2 vv = *reinterpret_cast<const float2*>(V  + (size_t)s*64 + lane*2);
        float g0 = __fdividef(1.f, 1.f + __expf(-ev.x));
        float g1 = __fdividef(1.f, 1.f + __expf(-ev.y));
        float a = vv.x*g0, b = vv.y*g1;
        s0 += a; s1 += b; m0 = fmaxf(m0,a); m1 = fmaxf(m1,b);
    }
    if (beg == end){ m0 = 0.f; m1 = 0.f; }
    size_t o = (size_t)warp*64 + lane*2;
    aggS[o]=s0; aggS[o+1]=s1; aggM[o]=m0; aggM[o+1]=m1;
}

// ---------- stats reduce ----------
static __device__ __forceinline__ void stat_reduce(float s0, float s1, float q0, float q1,
                                                   float* sSum, float* sSq, int col, int lane){
    #pragma unroll
    for (int off = 4; off < 32; off <<= 1){
        s0 += __shfl_xor_sync(0xFFFFFFFFu, s0, off);
        s1 += __shfl_xor_sync(0xFFFFFFFFu, s1, off);
        q0 += __shfl_xor_sync(0xFFFFFFFFu, q0, off);
        q1 += __shfl_xor_sync(0xFFFFFFFFu, q1, off);
    }
    if (lane < 4){
        atomicAdd(&sSum[col],   s0);
        atomicAdd(&sSum[col+1], s1);
        atomicAdd(&sSq[col],    q0);
        atomicAdd(&sSq[col+1],  q1);
    }
}

// ---------- 3-candidate mixed GEMM: 128 threads, 4 warps, M32xN64 per warp ----------
// smem: A hi@0 lo@18432 (36864); B cand p: hi@36864+p*18432, lo=+9216 (end 92160)
//       sSum@92160 (192f), sSq@92928 -> 93696 total
template<bool EDGE>
__global__ void __launch_bounds__(128,2)
mm_gemm3(const float* __restrict__ A0, const float* __restrict__ A1,
         const float* __restrict__ A2,
         const int* __restrict__ srcI, const int* __restrict__ dstI,
         const float* __restrict__ W, float* __restrict__ Y,
         float* __restrict__ statsOut, int rows)
{
    extern __shared__ __align__(16) unsigned char sm[];
    float* sSum = (float*)(sm + 92160);
    float* sSq  = (float*)(sm + 92928);
    int tid = threadIdx.x, wid = tid>>5, lane = tid&31;
    int r0 = blockIdx.x*128;
    for (int i = tid; i < 192; i += 128){ sSum[i]=0.f; sSq[i]=0.f; }

    for (int idx = tid; idx < 12288; idx += 128){
        int p = idx>>12, k = (idx>>6)&63, n = idx&63;
        __nv_bfloat16 h,l; wsplit(W[p*4096 + k*64 + n], &h, &l);
        unsigned char* base = sm + 36864 + p*18432;
        uint32_t off = (uint32_t)(n*AST + k)*2;
        *(__nv_bfloat16*)(base + off) = h;
        *(__nv_bfloat16*)(base + 9216 + off) = l;
    }

    int lr = tid;             // one full row per thread
    int gr = r0 + lr;
    bool ok = gr < rows;
    int sidx = 0, didx = 0;
    if (EDGE){ sidx = ok ? srcI[gr] : 0; didx = ok ? dstI[gr] : 0; }
    int mrow = wid*32;
    int g = lane>>2, t2 = (lane&3)*2;

    #pragma unroll 1
    for (int p = 0; p < 3; p++){
        // build candidate p (whole row per thread)
        {
            float4 z = make_float4(0,0,0,0);
            unsigned char* H = sm; unsigned char* L = sm + 18432;
            if (EDGE){
                const float4* pe = (const float4*)(A0 + (size_t)gr*64);
                const float4* ps = (const float4*)(A1 + (size_t)sidx*64);
                const float4* pd = (const float4*)(A1 + (size_t)didx*64);
                #pragma unroll
                for (int i = 0; i < 16; i++){
                    int c = i*4;
                    if (p == 0){
                        float4 e = ok ? pe[i] : z;
                        st2(H,L,lr,c, e.x,e.y); st2(H,L,lr,c+2, e.z,e.w);
                    } else if (p == 1){
                        float4 e = ok ? pe[i] : z;
                        float4 a = ok ? ps[i] : z;
                        float4 b = ok ? pd[i] : z;
                        st2(H,L,lr,c,   e.x+a.x+b.x, e.y+a.y+b.y);
                        st2(H,L,lr,c+2, e.z+a.z+b.z, e.w+a.w+b.w);
                    } else {
                        float4 a = ok ? ps[i] : z;
                        float4 b = ok ? pd[i] : z;
                        st2(H,L,lr,c,   a.x*b.x, a.y*b.y);
                        st2(H,L,lr,c+2, a.z*b.z, a.w*b.w);
                    }
                }
            } else {
                const float* Ap = (p==0) ? A0 : (p==1) ? A1 : A2;
                const float4* ps = (const float4*)(Ap + (size_t)gr*64);
                #pragma unroll
                for (int i = 0; i < 16; i++){
                    int c = i*4;
                    float4 v = ok ? ps[i] : z;
                    st2(H,L,lr,c, v.x,v.y); st2(H,L,lr,c+2, v.z,v.w);
                }
            }
        }
        __syncthreads();

        const unsigned char* Ah = sm;
        const unsigned char* Al = sm + 18432;
        const unsigned char* Bh = sm + 36864 + p*18432;
        const unsigned char* Bl = Bh + 9216;
        float acc[2][8][4];
        #pragma unroll
        for (int s = 0; s < 2; s++)
            #pragma unroll
            for (int j = 0; j < 8; j++){ acc[s][j][0]=0;acc[s][j][1]=0;acc[s][j][2]=0;acc[s][j][3]=0; }
        #pragma unroll
        for (int kt = 0; kt < 4; kt++){
            uint32_t ah[2][4], al[2][4];
            ldA(ah[0], Ah, mrow,      kt*16, lane);
            ldA(ah[1], Ah, mrow + 16, kt*16, lane);
            ldA(al[0], Al, mrow,      kt*16, lane);
            ldA(al[1], Al, mrow + 16, kt*16, lane);
            #pragma unroll
            for (int j = 0; j < 8; j++){
                uint32_t bh[2], bl[2];
                ldB(bh, Bh, j*8, kt*16, lane);
                ldB(bl, Bl, j*8, kt*16, lane);
                #pragma unroll
                for (int s = 0; s < 2; s++){
                    mma_bf16(acc[s][j], ah[s], bh);
                    mma_bf16(acc[s][j], al[s], bh);
                    mma_bf16(acc[s][j], ah[s], bl);
                }
            }
        }
        __syncthreads();   // all mma reads done before next candidate build

        #pragma unroll
        for (int j = 0; j < 8; j++){
            int col = p*64 + j*8 + t2;
            #pragma unroll
            for (int s = 0; s < 2; s++){
                int row0 = r0 + mrow + s*16 + g, row1 = row0 + 8;
                if (row0 < rows){ float2 v; v.x=acc[s][j][0]; v.y=acc[s][j][1]; *(float2*)(Y + (size_t)row0*192 + col) = v; }
                if (row1 < rows){ float2 v; v.x=acc[s][j][2]; v.y=acc[s][j][3]; *(float2*)(Y + (size_t)row1*192 + col) = v; }
            }
            stat_reduce(acc[0][j][0]+acc[0][j][2]+acc[1][j][0]+acc[1][j][2],
                        acc[0][j][1]+acc[0][j][3]+acc[1][j][1]+acc[1][j][3],
                        acc[0][j][0]*acc[0][j][0]+acc[0][j][2]*acc[0][j][2]+acc[1][j][0]*acc[1][j][0]+acc[1][j][2]*acc[1][j][2],
                        acc[0][j][1]*acc[0][j][1]+acc[0][j][3]*acc[0][j][3]+acc[1][j][1]*acc[1][j][1]+acc[1][j][3]*acc[1][j][3],
                        sSum, sSq, col, lane);
        }
    }
    __syncthreads();
    for (int i = tid; i < 192; i += 128){
        atomicAdd(statsOut + i, sSum[i]);
        atomicAdd(statsOut + 192 + i, sSq[i]);
    }
}

// ---------- final GEMM1 [256->128], B streamed per K-chunk (occ 2) ----------
__global__ void __launch_bounds__(256,2)
mm_final1(const float* __restrict__ S0, const float* __restrict__ S1,
          const float* __restrict__ S2, const float* __restrict__ S3,
          const float* __restrict__ W1, float* __restrict__ Yf,
          float* __restrict__ statsOut, int rows)
{
    extern __shared__ __align__(16) unsigned char sm[];
    float* sSum = (float*)(sm + 73728);
    float* sSq  = (float*)(sm + 74240);
    int tid = threadIdx.x, wid = tid>>5, lane = tid&31;
    int r0 = blockIdx.x*128;
    if (tid < 128){ sSum[tid]=0.f; sSq[tid]=0.f; }

    const float* Ss[4] = {S0,S1,S2,S3};
    int mrow = wid*16;
    int g = lane>>2, t2 = (lane&3)*2;
    float acc[16][4];
    #pragma unroll
    for (int j = 0; j < 16; j++){ acc[j][0]=0;acc[j][1]=0;acc[j][2]=0;acc[j][3]=0; }

    #pragma unroll 1
    for (int kc = 0; kc < 4; kc++){
        {
            int lr = tid >> 1, half = tid & 1;
            int gr = r0 + lr;
            bool ok = gr < rows;
            float4 z = make_float4(0,0,0,0);
            const float4* ps = (const float4*)(Ss[kc] + (size_t)gr*64);
            #pragma unroll
            for (int i = 0; i < 8; i++){
                int c = half*32 + i*4;
                float4 v = ok ? ps[c>>2] : z;
                st2(sm, sm+18432, lr, c,   leakyf(v.x), leakyf(v.y));
                st2(sm, sm+18432, lr, c+2, leakyf(v.z), leakyf(v.w));
            }
            for (int idx = tid; idx < 8192; idx += 256){
                int k = idx>>7, n = idx&127;
                __nv_bfloat16 h,l; wsplit(W1[(size_t)(kc*64+k)*128 + n], &h, &l);
                uint32_t off = (uint32_t)(n*AST + k)*2;
                *(__nv_bfloat16*)(sm + 36864 + off) = h;
                *(__nv_bfloat16*)(sm + 55296 + off) = l;
            }
        }
        __syncthreads();
        const unsigned char* Ah = sm;
        const unsigned char* Al = sm + 18432;
        const unsigned char* Bh = sm + 36864;
        const unsigned char* Bl = sm + 55296;
        #pragma unroll
        for (int kt = 0; kt < 4; kt++){
            uint32_t ah[4], al[4];
            ldA(ah, Ah, mrow, kt*16, lane);
            ldA(al, Al, mrow, kt*16, lane);
            #pragma unroll
            for (int j = 0; j < 16; j++){
                uint32_t bh[2], bl[2];
                ldB(bh, Bh, j*8, kt*16, lane);
                ldB(bl, Bl, j*8, kt*16, lane);
                mma_bf16(acc[j], ah, bh);
                mma_bf16(acc[j], al, bh);
                mma_bf16(acc[j], ah, bl);
            }
        }
        __syncthreads();
    }
    #pragma unroll
    for (int j = 0; j < 16; j++){
        int col = j*8 + t2;
        int row0 = r0 + mrow + g, row1 = row0 + 8;
        if (row0 < rows){ float2 v; v.x=acc[j][0]; v.y=acc[j][1]; *(float2*)(Yf + (size_t)row0*128 + col) = v; }
        if (row1 < rows){ float2 v; v.x=acc[j][2]; v.y=acc[j][3]; *(float2*)(Yf + (size_t)row1*128 + col) = v; }
        stat_reduce(acc[j][0]+acc[j][2], acc[j][1]+acc[j][3],
                    acc[j][0]*acc[j][0]+acc[j][2]*acc[j][2],
                    acc[j][1]*acc[j][1]+acc[j][3]*acc[j][3],
                    sSum, sSq, col, lane);
    }
    __syncthreads();
    if (tid < 128){
        atomicAdd(statsOut + tid, sSum[tid]);
        atomicAdd(statsOut + 192 + tid, sSq[tid]);
    }
}

// ---------- final GEMM2 [128->64] (occ 2) ----------
__global__ void __launch_bounds__(256,2)
mm_final2(const float* __restrict__ Yf, int w, const float* __restrict__ W2,
          float* __restrict__ outp, int rows)
{
    extern __shared__ __align__(16) unsigned char sm[];
    int tid = threadIdx.x, wid = tid>>5, lane = tid&31;
    int r0 = blockIdx.x*128;

    for (int idx = tid; idx < 8192; idx += 256){
        int cc = idx>>12, k = (idx>>6)&63, n = idx&63;
        __nv_bfloat16 h,l; wsplit(W2[(size_t)(cc*64+k)*64 + n], &h, &l);
        unsigned char* base = sm + 36864 + cc*18432;
        uint32_t off = (uint32_t)(n*AST + k)*2;
        *(__nv_bfloat16*)(base + off) = h;
        *(__nv_bfloat16*)(base + 9216 + off) = l;
    }

    int mrow = wid*16;
    int g = lane>>2, t2 = (lane&3)*2;
    float acc[8][4];
    #pragma unroll
    for (int j = 0; j < 8; j++){ acc[j][0]=0;acc[j][1]=0;acc[j][2]=0;acc[j][3]=0; }

    #pragma unroll 1
    for (int cc = 0; cc < 2; cc++){
        __syncthreads();
        {
            int lr = tid >> 1, half = tid & 1;
            int gr = r0 + lr;
            bool ok = gr < rows;
            float4 z = make_float4(0,0,0,0);
            const float4* py = (const float4*)(Yf + (size_t)gr*128);
            #pragma unroll
            for (int i = 0; i < 8; i++){
                int c = half*32 + i*4;
                int kg = cc*64 + c;
                float4 v = ok ? py[kg>>2] : z;
                float4 m  = *(const float4*)(&g_fmean[w][kg]);
                float4 iv = *(const float4*)(&g_finv[w][kg]);
                st2(sm, sm+18432, lr, c,   leakyf((v.x-m.x)*iv.x), leakyf((v.y-m.y)*iv.y));
                st2(sm, sm+18432, lr, c+2, leakyf((v.z-m.z)*iv.z), leakyf((v.w-m.w)*iv.w));
            }
        }
        __syncthreads();
        const unsigned char* Ah = sm;
        const unsigned char* Al = sm + 18432;
        const unsigned char* Bh = sm + 36864 + cc*18432;
        const unsigned char* Bl = Bh + 9216;
        #pragma unroll
        for (int kt = 0; kt < 4; kt++){
            uint32_t ah[4], al[4];
            ldA(ah, Ah, mrow, kt*16, lane);
            ldA(al, Al, mrow, kt*16, lane);
            #pragma unroll
            for (int j = 0; j < 8; j++){
                uint32_t bh[2], bl[2];
                ldB(bh, Bh, j*8, kt*16, lane);
                ldB(bl, Bl, j*8, kt*16, lane);
                mma_bf16(acc[j], ah, bh);
                mma_bf16(acc[j], al, bh);
                mma_bf16(acc[j], ah, bl);
            }
        }
    }
    #pragma unroll
    for (int j = 0; j < 8; j++){
        int col = j*8 + t2;
        int row0 = r0 + mrow + g, row1 = row0 + 8;
        if (row0 < rows){ float2 v; v.x=acc[j][0]; v.y=acc[j][1]; *(float2*)(outp + (size_t)row0*64 + col) = v; }
        if (row1 < rows){ float2 v; v.x=acc[j][2]; v.y=acc[j][3]; *(float2*)(outp + (size_t)row1*64 + col) = v; }
    }
}

// ---------- BN finalize / normalize ----------
__global__ void k_finalize(int linkBase, float rowsInv){
    int link = linkBase + blockIdx.x;
    int c = threadIdx.x;
    float m = g_stats[link][0][c]*rowsInv;
    float var = g_stats[link][1][c]*rowsInv - m*m;
    float inv = rsqrtf(var + EPS);
    float sc = g_softp[link][c>>6]*inv;
    g_scale[link][c] = sc;
    g_shift[link][c] = -m*sc;
}

__global__ void __launch_bounds__(256)
k_norm2(const float* __restrict__ YA, int lA,
        const float* __restrict__ YB, int lB,
        float* __restrict__ out, int rows)
{
    __shared__ float sc[2][192], sh[2][192];
    int tid = threadIdx.x;
    for (int i = tid; i < 192; i += 256){
        sc[0][i]=g_scale[lA][i]; sh[0][i]=g_shift[lA][i];
        sc[1][i]=g_scale[lB][i]; sh[1][i]=g_shift[lB][i];
    }
    __syncthreads();
    long idx = (long)blockIdx.x*blockDim.x + tid;
    if (idx >= (long)rows*16) return;
    long row = idx >> 4;
    int d = (int)(idx & 15)*4;
    const float4* a = (const float4*)(YA + row*192);
    const float4* b = (const float4*)(YB + row*192);
    float4 o = make_float4(0,0,0,0);
    #pragma unroll
    for (int i = 0; i < 3; i++){
        int c = i*64 + d;
        float4 ya = a[c>>2], yb = b[c>>2];
        o.x += ya.x*sc[0][c+0]+sh[0][c+0] + yb.x*sc[1][c+0]+sh[1][c+0];
        o.y += ya.y*sc[0][c+1]+sh[0][c+1] + yb.y*sc[1][c+1]+sh[1][c+1];
        o.z += ya.z*sc[0][c+2]+sh[0][c+2] + yb.z*sc[1][c+2]+sh[1][c+2];
        o.w += ya.w*sc[0][c+3]+sh[0][c+3] + yb.w*sc[1][c+3]+sh[1][c+3];
    }
    *(float4*)(out + row*64 + d) = o;
}

__global__ void k_finalizeF(int idx, float rowsInv, int w){
    int c = threadIdx.x;
    const float* st = &g_stats[idx][0][0];
    float m = st[c]*rowsInv;
    float var = st[192+c]*rowsInv - m*m;
    g_fmean[w][c] = m;
    g_finv[w][c] = rsqrtf(var + EPS);
}

// ---------- host ----------
extern "C" void kernel_launch(void* const* d_in, const int* in_sizes, int n_in,
                              void* d_out, int out_size) {
    (void)in_sizes; (void)n_in; (void)out_size;
    const float* V0 = (const float*)d_in[0];
    const float* V1 = (const float*)d_in[1];
    const float* E0 = (const float*)d_in[2];
    const float* E1 = (const float*)d_in[3];
    const int*  src = (const int*)d_in[4];
    const int*  dst = (const int*)d_in[5];
    const float* arch = (const float*)d_in[6];
    const float* Wv  = (const float*)d_in[7];
    const float* We  = (const float*)d_in[8];
    const float* Wv1 = (const float*)d_in[9];
    const float* Wv2 = (const float*)d_in[10];
    const float* We1 = (const float*)d_in[11];
    const float* We2 = (const float*)d_in[12];
    float* outV = (float*)d_out;
    float* outE = outV + (size_t)NN*64;

    const int SM_G3 = 93696, SM_F1 = 74752, SM_F2 = 73728;
    cudaFuncSetAttribute(mm_gemm3<true>,  cudaFuncAttributeMaxDynamicSharedMemorySize, SM_G3);
    cudaFuncSetAttribute(mm_gemm3<false>, cudaFuncAttributeMaxDynamicSharedMemorySize, SM_G3);
    cudaFuncSetAttribute(mm_final1, cudaFuncAttributeMaxDynamicSharedMemorySize, SM_F1);
    cudaFuncSetAttribute(mm_final2, cudaFuncAttributeMaxDynamicSharedMemorySize, SM_F2);

    float *YvA,*YvB,*YeA,*YeB,*V2,*V3,*E2,*E3,*aSA,*aMA,*aSB,*aMB,*Yfv,*Yfe,*stats;
    cudaGetSymbolAddress((void**)&YvA, g_YvA);
    cudaGetSymbolAddress((void**)&YvB, g_YvB);
    cudaGetSymbolAddress((void**)&YeA, g_YeA);
    cudaGetSymbolAddress((void**)&YeB, g_YeB);
    cudaGetSymbolAddress((void**)&V2,  g_V2);
    cudaGetSymbolAddress((void**)&V3,  g_V3);
    cudaGetSymbolAddress((void**)&E2,  g_E2);
    cudaGetSymbolAddress((void**)&E3,  g_E3);
    cudaGetSymbolAddress((void**)&aSA, g_aggSA);
    cudaGetSymbolAddress((void**)&aMA, g_aggMA);
    cudaGetSymbolAddress((void**)&aSB, g_aggSB);
    cudaGetSymbolAddress((void**)&aMB, g_aggMB);
    cudaGetSymbolAddress((void**)&Yfv, g_Yfv);
    cudaGetSymbolAddress((void**)&Yfe, g_Yfe);
    cudaGetSymbolAddress((void**)&stats, g_stats);
    #define STATS(i) (stats + (size_t)(i)*384)

    const int NBN = (NN + 127)/128, NBE = NE/128;
    const float invN = 1.f/NN, invE = 1.f/NE;

    k_prep<<<196,256>>>(arch);
    k_count<<<(NE+255)/256,256>>>(dst);
    mm_gemm3<true><<<NBE,128,SM_G3>>>(E0, V0, nullptr, src, dst, We + 0*12288, YeA, STATS(4), NE);
    mm_gemm3<true><<<NBE,128,SM_G3>>>(E1, V1, nullptr, src, dst, We + 1*12288, YeB, STATS(5), NE);
    k_finalize<<<2,192>>>(4, invE);
    k_norm2<<<(NE*16+255)/256,256>>>(YeA, 4, YeB, 5, E2, NE);

    k_scan<<<1,1024>>>();
    k_scatter<<<(NE+255)/256,256>>>(src,dst);
    k_agg<<<(NN*32+255)/256,256>>>(E0, V0, aSA, aMA);
    k_agg<<<(NN*32+255)/256,256>>>(E1, V1, aSB, aMB);

    mm_gemm3<false><<<NBN,128,SM_G3>>>(V0, aSA, aMA, nullptr, nullptr, Wv + 0*12288, YvA, STATS(0), NN);
    mm_gemm3<false><<<NBN,128,SM_G3>>>(V1, aSB, aMB, nullptr, nullptr, Wv + 1*12288, YvB, STATS(1), NN);
    k_finalize<<<2,192>>>(0, invN);
    k_norm2<<<(NN*16+255)/256,256>>>(YvA, 0, YvB, 1, V2, NN);

    k_agg<<<(NN*32+255)/256,256>>>(E2, V2, aSA, aMA);

    mm_gemm3<false><<<NBN,128,SM_G3>>>(V1, aSB, aMB, nullptr, nullptr, Wv + 2*12288, YvA, STATS(2), NN);
    mm_gemm3<false><<<NBN,128,SM_G3>>>(V2, aSA, aMA, nullptr, nullptr, Wv + 3*12288, YvB, STATS(3), NN);
    k_finalize<<<2,192>>>(2, invN);
    k_norm2<<<(NN*16+255)/256,256>>>(YvA, 2, YvB, 3, V3, NN);

    mm_gemm3<true><<<NBE,128,SM_G3>>>(E1, V1, nullptr, src, dst, We + 2*12288, YeA, STATS(6), NE);
    mm_gemm3<true><<<NBE,128,SM_G3>>>(E2, V2, nullptr, src, dst, We + 3*12288, YeB, STATS(7), NE);
    k_finalize<<<2,192>>>(6, invE);
    k_norm2<<<(NE*16+255)/256,256>>>(YeA, 6, YeB, 7, E3, NE);

    mm_final1<<<NBN,256,SM_F1>>>(V0, V1, V2, V3, Wv1, Yfv, STATS(8), NN);
    k_finalizeF<<<1,128>>>(8, invN, 0);
    mm_final2<<<NBN,256,SM_F2>>>(Yfv, 0, Wv2, outV, NN);

    mm_final1<<<NBE,256,SM_F1>>>(E0, E1, E2, E3, We1, Yfe, STATS(9), NE);
    k_finalizeF<<<1,128>>>(9, invE, 1);
    mm_final2<<<NBE,256,SM_F2>>>(Yfe, 1, We2, outE, NE);
    #undef STATS
}

// round 15
// speedup vs baseline: 1.0176x; 1.0176x over previous
#include <cuda_runtime.h>
#include <cuda_bf16.h>
#include <math.h>
#include <stdint.h>

#define NN 50000
#define NE 800000
#define EPS 1e-5f
#define AST 72

// ---------- static scratch ----------
__device__ __align__(16) float g_V2[NN*64];
__device__ __align__(16) float g_V3[NN*64];
__device__ __align__(16) float g_aggSA[NN*64];
__device__ __align__(16) float g_aggMA[NN*64];
__device__ __align__(16) float g_aggSB[NN*64];
__device__ __align__(16) float g_aggMB[NN*64];
__device__ __align__(16) float g_YvA[(size_t)NN*192];
__device__ __align__(16) float g_YvB[(size_t)NN*192];
__device__ __align__(16) float g_E2[(size_t)NE*64];
__device__ __align__(16) float g_E3[(size_t)NE*64];
__device__ __align__(16) float g_YeA[(size_t)NE*192];
__device__ __align__(16) float g_YeB[(size_t)NE*192];
__device__ __align__(16) float g_Yfv[(size_t)NN*128];
__device__ __align__(16) float g_Yfe[(size_t)NE*128];
__device__ int   g_deg[NN];
__device__ int   g_rowptr[NN+1];
__device__ int   g_cursor[NN];
__device__ int   g_perm[NE];
__device__ int   g_srcPerm[NE];
__device__ __align__(16) float g_softp[8][3];
__device__ __align__(16) float g_stats[10][2][192];
__device__ __align__(16) float g_scale[8][192];
__device__ __align__(16) float g_shift[8][192];
__device__ __align__(16) float g_fmean[2][128];
__device__ __align__(16) float g_finv[2][128];

__device__ __forceinline__ float leakyf(float x){ return x > 0.f ? x : 0.2f*x; }

// ---------- mma.sync helpers ----------
static __device__ __forceinline__ void mma_bf16(float* d, const uint32_t* a, const uint32_t* b){
    asm volatile("mma.sync.aligned.m16n8k16.row.col.f32.bf16.bf16.f32 "
        "{%0,%1,%2,%3}, {%4,%5,%6,%7}, {%8,%9}, {%0,%1,%2,%3};"
        : "+f"(d[0]),"+f"(d[1]),"+f"(d[2]),"+f"(d[3])
        : "r"(a[0]),"r"(a[1]),"r"(a[2]),"r"(a[3]),"r"(b[0]),"r"(b[1]));
}
static __device__ __forceinline__ void ldA(uint32_t* a, const unsigned char* base, int mrow, int k0, int lane){
    int g = lane>>2, t2 = (lane&3)*2;
    const unsigned char* p = base + (size_t)((mrow+g)*AST + k0 + t2)*2;
    a[0] = *(const uint32_t*)p;
    a[2] = *(const uint32_t*)(p + 16);
    const unsigned char* q = p + 8*AST*2;
    a[1] = *(const uint32_t*)q;
    a[3] = *(const uint32_t*)(q + 16);
}
static __device__ __forceinline__ void ldB(uint32_t* b, const unsigned char* base, int n0, int k0, int lane){
    int g = lane>>2, t2 = (lane&3)*2;
    const unsigned char* p = base + (size_t)((n0+g)*AST + k0 + t2)*2;
    b[0] = *(const uint32_t*)p;
    b[1] = *(const uint32_t*)(p + 16);
}
static __device__ __forceinline__ void st2(unsigned char* H, unsigned char* L, int row, int col, float v0, float v1){
    uint32_t off = (uint32_t)(row*AST + col)*2;
    __nv_bfloat16 h0=__float2bfloat16(v0), h1=__float2bfloat16(v1);
    __nv_bfloat16 l0=__float2bfloat16(v0-__bfloat162float(h0));
    __nv_bfloat16 l1=__float2bfloat16(v1-__bfloat162float(h1));
    __nv_bfloat162 th; th.x=h0; th.y=h1;
    __nv_bfloat162 tl; tl.x=l0; tl.y=l1;
    *(__nv_bfloat162*)(H+off)=th;
    *(__nv_bfloat162*)(L+off)=tl;
}
static __device__ __forceinline__ void wsplit(float w, __nv_bfloat16* h, __nv_bfloat16* l){
    *h = __float2bfloat16(w);
    *l = __float2bfloat16(w - __bfloat162float(*h));
}

// ---------- setup ----------
__global__ void k_prep(const float* __restrict__ arch){
    int idx = blockIdx.x*blockDim.x + threadIdx.x;
    if (idx < NN) g_deg[idx] = 0;
    if (idx < 10*2*192) (&g_stats[0][0][0])[idx] = 0.f;
    if (idx < 8){
        float a0=arch[idx*3+0], a1=arch[idx*3+1], a2=arch[idx*3+2];
        float mx=fmaxf(a0,fmaxf(a1,a2));
        float e0=__expf(a0-mx), e1=__expf(a1-mx), e2=__expf(a2-mx);
        float s=e0+e1+e2;
        g_softp[idx][0]=e0/s; g_softp[idx][1]=e1/s; g_softp[idx][2]=e2/s;
    }
}
__global__ void k_count(const int* __restrict__ dst){
    int e = blockIdx.x*blockDim.x + threadIdx.x;
    if (e < NE) atomicAdd(&g_deg[dst[e]], 1);
}
__global__ void k_scan(){
    __shared__ int part[1024];
    int tid = threadIdx.x;
    const int CH = (NN + 1023)/1024;
    int base = tid*CH, s = 0;
    for (int i = 0; i < CH; i++){ int ix = base+i; if (ix < NN) s += g_deg[ix]; }
    part[tid] = s; __syncthreads();
    for (int off = 1; off < 1024; off <<= 1){
        int v = part[tid];
        int add = (tid >= off) ? part[tid-off] : 0;
        __syncthreads(); part[tid] = v + add; __syncthreads();
    }
    int run = (tid == 0) ? 0 : part[tid-1];
    for (int i = 0; i < CH; i++){
        int ix = base+i;
        if (ix < NN){ g_rowptr[ix]=run; g_cursor[ix]=run; run += g_deg[ix]; }
    }
    if (tid == 1023) g_rowptr[NN] = part[1023];
}
__global__ void k_scatter(const int* __restrict__ src, const int* __restrict__ dst){
    int e = blockIdx.x*blockDim.x + threadIdx.x;
    if (e < NE){
        int d = dst[e];
        int pos = atomicAdd(&g_cursor[d], 1);
        g_perm[pos] = e;
        g_srcPerm[pos] = src[e];
    }
}

// ---------- aggregation ----------
__global__ void __launch_bounds__(256)
k_agg(const float* __restrict__ Es, const float* __restrict__ V,
      float* __restrict__ aggS, float* __restrict__ aggM)
{
    int warp = (blockIdx.x*blockDim.x + threadIdx.x) >> 5;
    int lane = threadIdx.x & 31;
    if (warp >= NN) return;
    int beg = g_rowptr[warp], end = g_rowptr[warp+1];
    float s0=0.f, s1=0.f, m0=-INFINITY, m1=-INFINITY;
    for (int i = beg; i < end; i++){
        int e = g_perm[i], s = g_srcPerm[i];
        float2 ev = *reinterpret_cast<const float2*>(Es + (size_t)e*64 + lane*2);
        float2 vv = *reinterpret_cast<const float2*>(V  + (size_t)s*64 + lane*2);
        float g0 = __fdividef(1.f, 1.f + __expf(-ev.x));
        float g1 = __fdividef(1.f, 1.f + __expf(-ev.y));
        float a = vv.x*g0, b = vv.y*g1;
        s0 += a; s1 += b; m0 = fmaxf(m0,a); m1 = fmaxf(m1,b);
    }
    if (beg == end){ m0 = 0.f; m1 = 0.f; }
    size_t o = (size_t)warp*64 + lane*2;
    aggS[o]=s0; aggS[o+1]=s1; aggM[o]=m0; aggM[o+1]=m1;
}

// ---------- stats reduce ----------
static __device__ __forceinline__ void stat_reduce(float s0, float s1, float q0, float q1,
                                                   float* sSum, float* sSq, int col, int lane){
    #pragma unroll
    for (int off = 4; off < 32; off <<= 1){
        s0 += __shfl_xor_sync(0xFFFFFFFFu, s0, off);
        s1 += __shfl_xor_sync(0xFFFFFFFFu, s1, off);
        q0 += __shfl_xor_sync(0xFFFFFFFFu, q0, off);
        q1 += __shfl_xor_sync(0xFFFFFFFFu, q1, off);
    }
    if (lane < 4){
        atomicAdd(&sSum[col],   s0);
        atomicAdd(&sSum[col+1], s1);
        atomicAdd(&sSq[col],    q0);
        atomicAdd(&sSq[col+1],  q1);
    }
}

// ---------- 3-candidate mixed GEMM, candidate-streamed (occ 2) ----------
// smem: A hi@0 lo@18432 (36864); B cand p: hi@36864+p*18432, lo=+9216 (end 92160)
//       sSum@92160 (192f), sSq@92928 -> 93696 total
template<bool EDGE>
__global__ void __launch_bounds__(256,2)
mm_gemm3(const float* __restrict__ A0, const float* __restrict__ A1,
         const float* __restrict__ A2,
         const int* __restrict__ srcI, const int* __restrict__ dstI,
         const float* __restrict__ W, float* __restrict__ Y,
         float* __restrict__ statsOut, int rows)
{
    extern __shared__ __align__(16) unsigned char sm[];
    float* sSum = (float*)(sm + 92160);
    float* sSq  = (float*)(sm + 92928);
    int tid = threadIdx.x, wid = tid>>5, lane = tid&31;
    int r0 = blockIdx.x*128;
    if (tid < 192){ sSum[tid]=0.f; sSq[tid]=0.f; }

    for (int idx = tid; idx < 12288; idx += 256){
        int p = idx>>12, k = (idx>>6)&63, n = idx&63;
        __nv_bfloat16 h,l; wsplit(W[p*4096 + k*64 + n], &h, &l);
        unsigned char* base = sm + 36864 + p*18432;
        uint32_t off = (uint32_t)(n*AST + k)*2;
        *(__nv_bfloat16*)(base + off) = h;
        *(__nv_bfloat16*)(base + 9216 + off) = l;
    }

    int lr = tid >> 1, half = tid & 1;
    int gr = r0 + lr;
    bool ok = gr < rows;
    int sidx = 0, didx = 0;
    if (EDGE){ sidx = ok ? srcI[gr] : 0; didx = ok ? dstI[gr] : 0; }
    int mrow = wid*16;
    int g = lane>>2, t2 = (lane&3)*2;

    #pragma unroll 1
    for (int p = 0; p < 3; p++){
        {
            float4 z = make_float4(0,0,0,0);
            unsigned char* H = sm; unsigned char* L = sm + 18432;
            if (EDGE){
                const float4* pe = (const float4*)(A0 + (size_t)gr*64);
                const float4* ps = (const float4*)(A1 + (size_t)sidx*64);
                const float4* pd = (const float4*)(A1 + (size_t)didx*64);
                #pragma unroll
                for (int i = 0; i < 8; i++){
                    int c = half*32 + i*4;
                    if (p == 0){
                        float4 e = ok ? pe[c>>2] : z;
                        st2(H,L,lr,c, e.x,e.y); st2(H,L,lr,c+2, e.z,e.w);
                    } else if (p == 1){
                        float4 e = ok ? pe[c>>2] : z;
                        float4 a = ok ? ps[c>>2] : z;
                        float4 b = ok ? pd[c>>2] : z;
                        st2(H,L,lr,c,   e.x+a.x+b.x, e.y+a.y+b.y);
                        st2(H,L,lr,c+2, e.z+a.z+b.z, e.w+a.w+b.w);
                    } else {
                        float4 a = ok ? ps[c>>2] : z;
                        float4 b = ok ? pd[c>>2] : z;
                        st2(H,L,lr,c,   a.x*b.x, a.y*b.y);
                        st2(H,L,lr,c+2, a.z*b.z, a.w*b.w);
                    }
                }
            } else {
                const float* Ap = (p==0) ? A0 : (p==1) ? A1 : A2;
                const float4* ps = (const float4*)(Ap + (size_t)gr*64);
                #pragma unroll
                for (int i = 0; i < 8; i++){
                    int c = half*32 + i*4;
                    float4 v = ok ? ps[c>>2] : z;
                    st2(H,L,lr,c, v.x,v.y); st2(H,L,lr,c+2, v.z,v.w);
                }
            }
        }
        __syncthreads();

        const unsigned char* Ah = sm;
        const unsigned char* Al = sm + 18432;
        const unsigned char* Bh = sm + 36864 + p*18432;
        const unsigned char* Bl = Bh + 9216;
        float acc[8][4];
        #pragma unroll
        for (int j = 0; j < 8; j++){ acc[j][0]=0;acc[j][1]=0;acc[j][2]=0;acc[j][3]=0; }
        #pragma unroll
        for (int kt = 0; kt < 4; kt++){
            uint32_t ah[4], al[4];
            ldA(ah, Ah, mrow, kt*16, lane);
            ldA(al, Al, mrow, kt*16, lane);
            #pragma unroll
            for (int j = 0; j < 8; j++){
                uint32_t bh[2], bl[2];
                ldB(bh, Bh, j*8, kt*16, lane);
                ldB(bl, Bl, j*8, kt*16, lane);
                mma_bf16(acc[j], ah, bh);
                mma_bf16(acc[j], al, bh);
                mma_bf16(acc[j], ah, bl);
            }
        }
        __syncthreads();   // all mma reads of A done before next build

        #pragma unroll
        for (int j = 0; j < 8; j++){
            int col = p*64 + j*8 + t2;
            int row0 = r0 + mrow + g, row1 = row0 + 8;
            if (row0 < rows){ float2 v; v.x=acc[j][0]; v.y=acc[j][1]; *(float2*)(Y + (size_t)row0*192 + col) = v; }
            if (row1 < rows){ float2 v; v.x=acc[j][2]; v.y=acc[j][3]; *(float2*)(Y + (size_t)row1*192 + col) = v; }
            stat_reduce(acc[j][0]+acc[j][2], acc[j][1]+acc[j][3],
                        acc[j][0]*acc[j][0]+acc[j][2]*acc[j][2],
                        acc[j][1]*acc[j][1]+acc[j][3]*acc[j][3],
                        sSum, sSq, col, lane);
        }
    }
    __syncthreads();
    if (tid < 192){
        atomicAdd(statsOut + tid, sSum[tid]);
        atomicAdd(statsOut + 192 + tid, sSq[tid]);
    }
}

// ---------- final GEMM1 [256->128], B streamed per K-chunk (occ 2) ----------
__global__ void __launch_bounds__(256,2)
mm_final1(const float* __restrict__ S0, const float* __restrict__ S1,
          const float* __restrict__ S2, const float* __restrict__ S3,
          const float* __restrict__ W1, float* __restrict__ Yf,
          float* __restrict__ statsOut, int rows)
{
    extern __shared__ __align__(16) unsigned char sm[];
    float* sSum = (float*)(sm + 73728);
    float* sSq  = (float*)(sm + 74240);
    int tid = threadIdx.x, wid = tid>>5, lane = tid&31;
    int r0 = blockIdx.x*128;
    if (tid < 128){ sSum[tid]=0.f; sSq[tid]=0.f; }

    const float* Ss[4] = {S0,S1,S2,S3};
    int mrow = wid*16;
    int g = lane>>2, t2 = (lane&3)*2;
    float acc[16][4];
    #pragma unroll
    for (int j = 0; j < 16; j++){ acc[j][0]=0;acc[j][1]=0;acc[j][2]=0;acc[j][3]=0; }

    #pragma unroll 1
    for (int kc = 0; kc < 4; kc++){
        {
            int lr = tid >> 1, half = tid & 1;
            int gr = r0 + lr;
            bool ok = gr < rows;
            float4 z = make_float4(0,0,0,0);
            const float4* ps = (const float4*)(Ss[kc] + (size_t)gr*64);
            #pragma unroll
            for (int i = 0; i < 8; i++){
                int c = half*32 + i*4;
                float4 v = ok ? ps[c>>2] : z;
                st2(sm, sm+18432, lr, c,   leakyf(v.x), leakyf(v.y));
                st2(sm, sm+18432, lr, c+2, leakyf(v.z), leakyf(v.w));
            }
            for (int idx = tid; idx < 8192; idx += 256){
                int k = idx>>7, n = idx&127;
                __nv_bfloat16 h,l; wsplit(W1[(size_t)(kc*64+k)*128 + n], &h, &l);
                uint32_t off = (uint32_t)(n*AST + k)*2;
                *(__nv_bfloat16*)(sm + 36864 + off) = h;
                *(__nv_bfloat16*)(sm + 55296 + off) = l;
            }
        }
        __syncthreads();
        const unsigned char* Ah = sm;
        const unsigned char* Al = sm + 18432;
        const unsigned char* Bh = sm + 36864;
        const unsigned char* Bl = sm + 55296;
        #pragma unroll
        for (int kt = 0; kt < 4; kt++){
            uint32_t ah[4], al[4];
            ldA(ah, Ah, mrow, kt*16, lane);
            ldA(al, Al, mrow, kt*16, lane);
            #pragma unroll
            for (int j = 0; j < 16; j++){
                uint32_t bh[2], bl[2];
                ldB(bh, Bh, j*8, kt*16, lane);
                ldB(bl, Bl, j*8, kt*16, lane);
                mma_bf16(acc[j], ah, bh);
                mma_bf16(acc[j], al, bh);
                mma_bf16(acc[j], ah, bl);
            }
        }
        __syncthreads();
    }
    #pragma unroll
    for (int j = 0; j < 16; j++){
        int col = j*8 + t2;
        int row0 = r0 + mrow + g, row1 = row0 + 8;
        if (row0 < rows){ float2 v; v.x=acc[j][0]; v.y=acc[j][1]; *(float2*)(Yf + (size_t)row0*128 + col) = v; }
        if (row1 < rows){ float2 v; v.x=acc[j][2]; v.y=acc[j][3]; *(float2*)(Yf + (size_t)row1*128 + col) = v; }
        stat_reduce(acc[j][0]+acc[j][2], acc[j][1]+acc[j][3],
                    acc[j][0]*acc[j][0]+acc[j][2]*acc[j][2],
                    acc[j][1]*acc[j][1]+acc[j][3]*acc[j][3],
                    sSum, sSq, col, lane);
    }
    __syncthreads();
    if (tid < 128){
        atomicAdd(statsOut + tid, sSum[tid]);
        atomicAdd(statsOut + 192 + tid, sSq[tid]);
    }
}

// ---------- final GEMM2 [128->64] (occ 2) ----------
__global__ void __launch_bounds__(256,2)
mm_final2(const float* __restrict__ Yf, int w, const float* __restrict__ W2,
          float* __restrict__ outp, int rows)
{
    extern __shared__ __align__(16) unsigned char sm[];
    int tid = threadIdx.x, wid = tid>>5, lane = tid&31;
    int r0 = blockIdx.x*128;

    for (int idx = tid; idx < 8192; idx += 256){
        int cc = idx>>12, k = (idx>>6)&63, n = idx&63;
        __nv_bfloat16 h,l; wsplit(W2[(size_t)(cc*64+k)*64 + n], &h, &l);
        unsigned char* base = sm + 36864 + cc*18432;
        uint32_t off = (uint32_t)(n*AST + k)*2;
        *(__nv_bfloat16*)(base + off) = h;
        *(__nv_bfloat16*)(base + 9216 + off) = l;
    }

    int mrow = wid*16;
    int g = lane>>2, t2 = (lane&3)*2;
    float acc[8][4];
    #pragma unroll
    for (int j = 0; j < 8; j++){ acc[j][0]=0;acc[j][1]=0;acc[j][2]=0;acc[j][3]=0; }

    #pragma unroll 1
    for (int cc = 0; cc < 2; cc++){
        __syncthreads();
        {
            int lr = tid >> 1, half = tid & 1;
            int gr = r0 + lr;
            bool ok = gr < rows;
            float4 z = make_float4(0,0,0,0);
            const float4* py = (const float4*)(Yf + (size_t)gr*128);
            #pragma unroll
            for (int i = 0; i < 8; i++){
                int c = half*32 + i*4;
                int kg = cc*64 + c;
                float4 v = ok ? py[kg>>2] : z;
                float4 m  = *(const float4*)(&g_fmean[w][kg]);
                float4 iv = *(const float4*)(&g_finv[w][kg]);
                st2(sm, sm+18432, lr, c,   leakyf((v.x-m.x)*iv.x), leakyf((v.y-m.y)*iv.y));
                st2(sm, sm+18432, lr, c+2, leakyf((v.z-m.z)*iv.z), leakyf((v.w-m.w)*iv.w));
            }
        }
        __syncthreads();
        const unsigned char* Ah = sm;
        const unsigned char* Al = sm + 18432;
        const unsigned char* Bh = sm + 36864 + cc*18432;
        const unsigned char* Bl = Bh + 9216;
        #pragma unroll
        for (int kt = 0; kt < 4; kt++){
            uint32_t ah[4], al[4];
            ldA(ah, Ah, mrow, kt*16, lane);
            ldA(al, Al, mrow, kt*16, lane);
            #pragma unroll
            for (int j = 0; j < 8; j++){
                uint32_t bh[2], bl[2];
                ldB(bh, Bh, j*8, kt*16, lane);
                ldB(bl, Bl, j*8, kt*16, lane);
                mma_bf16(acc[j], ah, bh);
                mma_bf16(acc[j], al, bh);
                mma_bf16(acc[j], ah, bl);
            }
        }
    }
    #pragma unroll
    for (int j = 0; j < 8; j++){
        int col = j*8 + t2;
        int row0 = r0 + mrow + g, row1 = row0 + 8;
        if (row0 < rows){ float2 v; v.x=acc[j][0]; v.y=acc[j][1]; *(float2*)(outp + (size_t)row0*64 + col) = v; }
        if (row1 < rows){ float2 v; v.x=acc[j][2]; v.y=acc[j][3]; *(float2*)(outp + (size_t)row1*64 + col) = v; }
    }
}

// ---------- BN finalize / normalize ----------
__global__ void k_finalize(int linkBase, float rowsInv){
    int link = linkBase + blockIdx.x;
    int c = threadIdx.x;
    float m = g_stats[link][0][c]*rowsInv;
    float var = g_stats[link][1][c]*rowsInv - m*m;
    float inv = rsqrtf(var + EPS);
    float sc = g_softp[link][c>>6]*inv;
    g_scale[link][c] = sc;
    g_shift[link][c] = -m*sc;
}

__global__ void __launch_bounds__(256)
k_norm2(const float* __restrict__ YA, int lA,
        const float* __restrict__ YB, int lB,
        float* __restrict__ out, int rows)
{
    __shared__ float sc[2][192], sh[2][192];
    int tid = threadIdx.x;
    for (int i = tid; i < 192; i += 256){
        sc[0][i]=g_scale[lA][i]; sh[0][i]=g_shift[lA][i];
        sc[1][i]=g_scale[lB][i]; sh[1][i]=g_shift[lB][i];
    }
    __syncthreads();
    long idx = (long)blockIdx.x*blockDim.x + tid;
    if (idx >= (long)rows*16) return;
    long row = idx >> 4;
    int d = (int)(idx & 15)*4;
    const float4* a = (const float4*)(YA + row*192);
    const float4* b = (const float4*)(YB + row*192);
    float4 o = make_float4(0,0,0,0);
    #pragma unroll
    for (int i = 0; i < 3; i++){
        int c = i*64 + d;
        float4 ya = a[c>>2], yb = b[c>>2];
        o.x += ya.x*sc[0][c+0]+sh[0][c+0] + yb.x*sc[1][c+0]+sh[1][c+0];
        o.y += ya.y*sc[0][c+1]+sh[0][c+1] + yb.y*sc[1][c+1]+sh[1][c+1];
        o.z += ya.z*sc[0][c+2]+sh[0][c+2] + yb.z*sc[1][c+2]+sh[1][c+2];
        o.w += ya.w*sc[0][c+3]+sh[0][c+3] + yb.w*sc[1][c+3]+sh[1][c+3];
    }
    *(float4*)(out + row*64 + d) = o;
}

__global__ void k_finalizeF(int idx, float rowsInv, int w){
    int c = threadIdx.x;
    const float* st = &g_stats[idx][0][0];
    float m = st[c]*rowsInv;
    float var = st[192+c]*rowsInv - m*m;
    g_fmean[w][c] = m;
    g_finv[w][c] = rsqrtf(var + EPS);
}

// ---------- host ----------
extern "C" void kernel_launch(void* const* d_in, const int* in_sizes, int n_in,
                              void* d_out, int out_size) {
    (void)in_sizes; (void)n_in; (void)out_size;
    const float* V0 = (const float*)d_in[0];
    const float* V1 = (const float*)d_in[1];
    const float* E0 = (const float*)d_in[2];
    const float* E1 = (const float*)d_in[3];
    const int*  src = (const int*)d_in[4];
    const int*  dst = (const int*)d_in[5];
    const float* arch = (const float*)d_in[6];
    const float* Wv  = (const float*)d_in[7];
    const float* We  = (const float*)d_in[8];
    const float* Wv1 = (const float*)d_in[9];
    const float* Wv2 = (const float*)d_in[10];
    const float* We1 = (const float*)d_in[11];
    const float* We2 = (const float*)d_in[12];
    float* outV = (float*)d_out;
    float* outE = outV + (size_t)NN*64;

    const int SM_G3 = 93696, SM_F1 = 74752, SM_F2 = 73728;
    cudaFuncSetAttribute(mm_gemm3<true>,  cudaFuncAttributeMaxDynamicSharedMemorySize, SM_G3);
    cudaFuncSetAttribute(mm_gemm3<false>, cudaFuncAttributeMaxDynamicSharedMemorySize, SM_G3);
    cudaFuncSetAttribute(mm_final1, cudaFuncAttributeMaxDynamicSharedMemorySize, SM_F1);
    cudaFuncSetAttribute(mm_final2, cudaFuncAttributeMaxDynamicSharedMemorySize, SM_F2);

    float *YvA,*YvB,*YeA,*YeB,*V2,*V3,*E2,*E3,*aSA,*aMA,*aSB,*aMB,*Yfv,*Yfe,*stats;
    cudaGetSymbolAddress((void**)&YvA, g_YvA);
    cudaGetSymbolAddress((void**)&YvB, g_YvB);
    cudaGetSymbolAddress((void**)&YeA, g_YeA);
    cudaGetSymbolAddress((void**)&YeB, g_YeB);
    cudaGetSymbolAddress((void**)&V2,  g_V2);
    cudaGetSymbolAddress((void**)&V3,  g_V3);
    cudaGetSymbolAddress((void**)&E2,  g_E2);
    cudaGetSymbolAddress((void**)&E3,  g_E3);
    cudaGetSymbolAddress((void**)&aSA, g_aggSA);
    cudaGetSymbolAddress((void**)&aMA, g_aggMA);
    cudaGetSymbolAddress((void**)&aSB, g_aggSB);
    cudaGetSymbolAddress((void**)&aMB, g_aggMB);
    cudaGetSymbolAddress((void**)&Yfv, g_Yfv);
    cudaGetSymbolAddress((void**)&Yfe, g_Yfe);
    cudaGetSymbolAddress((void**)&stats, g_stats);
    #define STATS(i) (stats + (size_t)(i)*384)

    const int NBN = (NN + 127)/128, NBE = NE/128;
    const float invN = 1.f/NN, invE = 1.f/NE;

    k_prep<<<196,256>>>(arch);
    k_count<<<(NE+255)/256,256>>>(dst);
    mm_gemm3<true><<<NBE,256,SM_G3>>>(E0, V0, nullptr, src, dst, We + 0*12288, YeA, STATS(4), NE);
    mm_gemm3<true><<<NBE,256,SM_G3>>>(E1, V1, nullptr, src, dst, We + 1*12288, YeB, STATS(5), NE);
    k_finalize<<<2,192>>>(4, invE);
    k_norm2<<<(NE*16+255)/256,256>>>(YeA, 4, YeB, 5, E2, NE);

    k_scan<<<1,1024>>>();
    k_scatter<<<(NE+255)/256,256>>>(src,dst);
    k_agg<<<(NN*32+255)/256,256>>>(E0, V0, aSA, aMA);
    k_agg<<<(NN*32+255)/256,256>>>(E1, V1, aSB, aMB);

    mm_gemm3<false><<<NBN,256,SM_G3>>>(V0, aSA, aMA, nullptr, nullptr, Wv + 0*12288, YvA, STATS(0), NN);
    mm_gemm3<false><<<NBN,256,SM_G3>>>(V1, aSB, aMB, nullptr, nullptr, Wv + 1*12288, YvB, STATS(1), NN);
    k_finalize<<<2,192>>>(0, invN);
    k_norm2<<<(NN*16+255)/256,256>>>(YvA, 0, YvB, 1, V2, NN);

    k_agg<<<(NN*32+255)/256,256>>>(E2, V2, aSA, aMA);

    mm_gemm3<false><<<NBN,256,SM_G3>>>(V1, aSB, aMB, nullptr, nullptr, Wv + 2*12288, YvA, STATS(2), NN);
    mm_gemm3<false><<<NBN,256,SM_G3>>>(V2, aSA, aMA, nullptr, nullptr, Wv + 3*12288, YvB, STATS(3), NN);
    k_finalize<<<2,192>>>(2, invN);
    k_norm2<<<(NN*16+255)/256,256>>>(YvA, 2, YvB, 3, V3, NN);

    mm_gemm3<true><<<NBE,256,SM_G3>>>(E1, V1, nullptr, src, dst, We + 2*12288, YeA, STATS(6), NE);
    mm_gemm3<true><<<NBE,256,SM_G3>>>(E2, V2, nullptr, src, dst, We + 3*12288, YeB, STATS(7), NE);
    k_finalize<<<2,192>>>(6, invE);
    k_norm2<<<(NE*16+255)/256,256>>>(YeA, 6, YeB, 7, E3, NE);

    mm_final1<<<NBN,256,SM_F1>>>(V0, V1, V2, V3, Wv1, Yfv, STATS(8), NN);
    k_finalizeF<<<1,128>>>(8, invN, 0);
    mm_final2<<<NBN,256,SM_F2>>>(Yfv, 0, Wv2, outV, NN);

    mm_final1<<<NBE,256,SM_F1>>>(E0, E1, E2, E3, We1, Yfe, STATS(9), NE);
    k_finalizeF<<<1,128>>>(9, invE, 1);
    mm_final2<<<NBE,256,SM_F2>>>(Yfe, 1, We2, outE, NE);
    #undef STATS
}

// round 16
// speedup vs baseline: 1.5889x; 1.5615x over previous
#include <cuda_runtime.h>
#include <cuda_bf16.h>
#include <math.h>
#include <stdint.h>

#define NN 50000
#define NE 800000
#define EPS 1e-5f
#define AST 72

// ---------- static scratch ----------
__device__ __align__(16) float g_V2[NN*64];
__device__ __align__(16) float g_V3[NN*64];
__device__ __align__(16) float g_aggSA[NN*64];
__device__ __align__(16) float g_aggMA[NN*64];
__device__ __align__(16) float g_aggSB[NN*64];
__device__ __align__(16) float g_aggMB[NN*64];
__device__ __align__(16) float g_YvA[(size_t)NN*192];
__device__ __align__(16) float g_YvB[(size_t)NN*192];
__device__ __align__(16) float g_E2[(size_t)NE*64];
__device__ __align__(16) float g_E3[(size_t)NE*64];
__device__ __align__(16) float g_YeA[(size_t)NE*192];
__device__ __align__(16) float g_YeB[(size_t)NE*192];
__device__ __align__(16) float g_Yfv[(size_t)NN*128];
__device__ __align__(16) float g_Yfe[(size_t)NE*128];
__device__ int   g_deg[NN];
__device__ int   g_rowptr[NN+1];
__device__ int   g_cursor[NN];
__device__ int   g_perm[NE];
__device__ int   g_srcPerm[NE];
__device__ __align__(16) float g_softp[8][3];
__device__ __align__(16) float g_stats[10][2][192];
__device__ __align__(16) float g_scale[8][192];
__device__ __align__(16) float g_shift[8][192];
__device__ __align__(16) float g_fmean[2][128];
__device__ __align__(16) float g_finv[2][128];

__device__ __forceinline__ float leakyf(float x){ return x > 0.f ? x : 0.2f*x; }

// ---------- mma.sync helpers ----------
static __device__ __forceinline__ void mma_bf16(float* d, const uint32_t* a, const uint32_t* b){
    asm volatile("mma.sync.aligned.m16n8k16.row.col.f32.bf16.bf16.f32 "
        "{%0,%1,%2,%3}, {%4,%5,%6,%7}, {%8,%9}, {%0,%1,%2,%3};"
        : "+f"(d[0]),"+f"(d[1]),"+f"(d[2]),"+f"(d[3])
        : "r"(a[0]),"r"(a[1]),"r"(a[2]),"r"(a[3]),"r"(b[0]),"r"(b[1]));
}
static __device__ __forceinline__ void ldA(uint32_t* a, const unsigned char* base, int mrow, int k0, int lane){
    int g = lane>>2, t2 = (lane&3)*2;
    const unsigned char* p = base + (size_t)((mrow+g)*AST + k0 + t2)*2;
    a[0] = *(const uint32_t*)p;
    a[2] = *(const uint32_t*)(p + 16);
    const unsigned char* q = p + 8*AST*2;
    a[1] = *(const uint32_t*)q;
    a[3] = *(const uint32_t*)(q + 16);
}
static __device__ __forceinline__ void ldB(uint32_t* b, const unsigned char* base, int n0, int k0, int lane){
    int g = lane>>2, t2 = (lane&3)*2;
    const unsigned char* p = base + (size_t)((n0+g)*AST + k0 + t2)*2;
    b[0] = *(const uint32_t*)p;
    b[1] = *(const uint32_t*)(p + 16);
}
static __device__ __forceinline__ void st2(unsigned char* H, unsigned char* L, int row, int col, float v0, float v1){
    uint32_t off = (uint32_t)(row*AST + col)*2;
    __nv_bfloat16 h0=__float2bfloat16(v0), h1=__float2bfloat16(v1);
    __nv_bfloat16 l0=__float2bfloat16(v0-__bfloat162float(h0));
    __nv_bfloat16 l1=__float2bfloat16(v1-__bfloat162float(h1));
    __nv_bfloat162 th; th.x=h0; th.y=h1;
    __nv_bfloat162 tl; tl.x=l0; tl.y=l1;
    *(__nv_bfloat162*)(H+off)=th;
    *(__nv_bfloat162*)(L+off)=tl;
}
static __device__ __forceinline__ void wsplit(float w, __nv_bfloat16* h, __nv_bfloat16* l){
    *h = __float2bfloat16(w);
    *l = __float2bfloat16(w - __bfloat162float(*h));
}

// ---------- setup ----------
__global__ void k_prep(const float* __restrict__ arch){
    int idx = blockIdx.x*blockDim.x + threadIdx.x;
    if (idx < NN) g_deg[idx] = 0;
    if (idx < 10*2*192) (&g_stats[0][0][0])[idx] = 0.f;
    if (idx < 8){
        float a0=arch[idx*3+0], a1=arch[idx*3+1], a2=arch[idx*3+2];
        float mx=fmaxf(a0,fmaxf(a1,a2));
        float e0=__expf(a0-mx), e1=__expf(a1-mx), e2=__expf(a2-mx);
        float s=e0+e1+e2;
        g_softp[idx][0]=e0/s; g_softp[idx][1]=e1/s; g_softp[idx][2]=e2/s;
    }
}
__global__ void k_count(const int* __restrict__ dst){
    int e = blockIdx.x*blockDim.x + threadIdx.x;
    if (e < NE) atomicAdd(&g_deg[dst[e]], 1);
}
__global__ void k_scan(){
    __shared__ int part[1024];
    int tid = threadIdx.x;
    const int CH = (NN + 1023)/1024;
    int base = tid*CH, s = 0;
    for (int i = 0; i < CH; i++){ int ix = base+i; if (ix < NN) s += g_deg[ix]; }
    part[tid] = s; __syncthreads();
    for (int off = 1; off < 1024; off <<= 1){
        int v = part[tid];
        int add = (tid >= off) ? part[tid-off] : 0;
        __syncthreads(); part[tid] = v + add; __syncthreads();
    }
    int run = (tid == 0) ? 0 : part[tid-1];
    for (int i = 0; i < CH; i++){
        int ix = base+i;
        if (ix < NN){ g_rowptr[ix]=run; g_cursor[ix]=run; run += g_deg[ix]; }
    }
    if (tid == 1023) g_rowptr[NN] = part[1023];
}
__global__ void k_scatter(const int* __restrict__ src, const int* __restrict__ dst){
    int e = blockIdx.x*blockDim.x + threadIdx.x;
    if (e < NE){
        int d = dst[e];
        int pos = atomicAdd(&g_cursor[d], 1);
        g_perm[pos] = e;
        g_srcPerm[pos] = src[e];
    }
}

// ---------- aggregation ----------
__global__ void __launch_bounds__(256)
k_agg(const float* __restrict__ Es, const float* __restrict__ V,
      float* __restrict__ aggS, float* __restrict__ aggM)
{
    int warp = (blockIdx.x*blockDim.x + threadIdx.x) >> 5;
    int lane = threadIdx.x & 31;
    if (warp >= NN) return;
    int beg = g_rowptr[warp], end = g_rowptr[warp+1];
    float s0=0.f, s1=0.f, m0=-INFINITY, m1=-INFINITY;
    for (int i = beg; i < end; i++){
        int e = g_perm[i], s = g_srcPerm[i];
        float2 ev = *reinterpret_cast<const float2*>(Es + (size_t)e*64 + lane*2);
        float2 vv = *reinterpret_cast<const float2*>(V  + (size_t)s*64 + lane*2);
        float g0 = __fdividef(1.f, 1.f + __expf(-ev.x));
        float g1 = __fdividef(1.f, 1.f + __expf(-ev.y));
        float a = vv.x*g0, b = vv.y*g1;
        s0 += a; s1 += b; m0 = fmaxf(m0,a); m1 = fmaxf(m1,b);
    }
    if (beg == end){ m0 = 0.f; m1 = 0.f; }
    size_t o = (size_t)warp*64 + lane*2;
    aggS[o]=s0; aggS[o+1]=s1; aggM[o]=m0; aggM[o+1]=m1;
}

// ---------- stats reduce ----------
static __device__ __forceinline__ void stat_reduce(float s0, float s1, float q0, float q1,
                                                   float* sSum, float* sSq, int col, int lane){
    #pragma unroll
    for (int off = 4; off < 32; off <<= 1){
        s0 += __shfl_xor_sync(0xFFFFFFFFu, s0, off);
        s1 += __shfl_xor_sync(0xFFFFFFFFu, s1, off);
        q0 += __shfl_xor_sync(0xFFFFFFFFu, q0, off);
        q1 += __shfl_xor_sync(0xFFFFFFFFu, q1, off);
    }
    if (lane < 4){
        atomicAdd(&sSum[col],   s0);
        atomicAdd(&sSum[col+1], s1);
        atomicAdd(&sSq[col],    q0);
        atomicAdd(&sSq[col+1],  q1);
    }
}

// ---------- 3-candidate mixed GEMM, candidate-streamed (occ 2), M32xN32 warp tiles ----------
// 8 warps in a 4x2 grid: mi=wid&3 (M32 strip), ni=wid>>2 (N32 half).
// smem: A hi@0 lo@18432 (36864); B cand p: hi@36864+p*18432, lo=+9216 (end 92160)
//       sSum@92160 (192f), sSq@92928 -> 93696 total
template<bool EDGE>
__global__ void __launch_bounds__(256,2)
mm_gemm3(const float* __restrict__ A0, const float* __restrict__ A1,
         const float* __restrict__ A2,
         const int* __restrict__ srcI, const int* __restrict__ dstI,
         const float* __restrict__ W, float* __restrict__ Y,
         float* __restrict__ statsOut, int rows)
{
    extern __shared__ __align__(16) unsigned char sm[];
    float* sSum = (float*)(sm + 92160);
    float* sSq  = (float*)(sm + 92928);
    int tid = threadIdx.x, wid = tid>>5, lane = tid&31;
    int r0 = blockIdx.x*128;
    if (tid < 192){ sSum[tid]=0.f; sSq[tid]=0.f; }

    for (int idx = tid; idx < 12288; idx += 256){
        int p = idx>>12, k = (idx>>6)&63, n = idx&63;
        __nv_bfloat16 h,l; wsplit(W[p*4096 + k*64 + n], &h, &l);
        unsigned char* base = sm + 36864 + p*18432;
        uint32_t off = (uint32_t)(n*AST + k)*2;
        *(__nv_bfloat16*)(base + off) = h;
        *(__nv_bfloat16*)(base + 9216 + off) = l;
    }

    int lr = tid >> 1, half = tid & 1;
    int gr = r0 + lr;
    bool ok = gr < rows;
    int sidx = 0, didx = 0;
    if (EDGE){ sidx = ok ? srcI[gr] : 0; didx = ok ? dstI[gr] : 0; }
    int mrow = (wid & 3)*32;
    int n0   = (wid >> 2)*32;
    int g = lane>>2, t2 = (lane&3)*2;

    #pragma unroll 1
    for (int p = 0; p < 3; p++){
        {
            float4 z = make_float4(0,0,0,0);
            unsigned char* H = sm; unsigned char* L = sm + 18432;
            if (EDGE){
                const float4* pe = (const float4*)(A0 + (size_t)gr*64);
                const float4* ps = (const float4*)(A1 + (size_t)sidx*64);
                const float4* pd = (const float4*)(A1 + (size_t)didx*64);
                #pragma unroll
                for (int i = 0; i < 8; i++){
                    int c = half*32 + i*4;
                    if (p == 0){
                        float4 e = ok ? pe[c>>2] : z;
                        st2(H,L,lr,c, e.x,e.y); st2(H,L,lr,c+2, e.z,e.w);
                    } else if (p == 1){
                        float4 e = ok ? pe[c>>2] : z;
                        float4 a = ok ? ps[c>>2] : z;
                        float4 b = ok ? pd[c>>2] : z;
                        st2(H,L,lr,c,   e.x+a.x+b.x, e.y+a.y+b.y);
                        st2(H,L,lr,c+2, e.z+a.z+b.z, e.w+a.w+b.w);
                    } else {
                        float4 a = ok ? ps[c>>2] : z;
                        float4 b = ok ? pd[c>>2] : z;
                        st2(H,L,lr,c,   a.x*b.x, a.y*b.y);
                        st2(H,L,lr,c+2, a.z*b.z, a.w*b.w);
                    }
                }
            } else {
                const float* Ap = (p==0) ? A0 : (p==1) ? A1 : A2;
                const float4* ps = (const float4*)(Ap + (size_t)gr*64);
                #pragma unroll
                for (int i = 0; i < 8; i++){
                    int c = half*32 + i*4;
                    float4 v = ok ? ps[c>>2] : z;
                    st2(H,L,lr,c, v.x,v.y); st2(H,L,lr,c+2, v.z,v.w);
                }
            }
        }
        __syncthreads();

        const unsigned char* Ah = sm;
        const unsigned char* Al = sm + 18432;
        const unsigned char* Bh = sm + 36864 + p*18432;
        const unsigned char* Bl = Bh + 9216;
        float acc[2][4][4];
        #pragma unroll
        for (int s = 0; s < 2; s++)
            #pragma unroll
            for (int j = 0; j < 4; j++){ acc[s][j][0]=0;acc[s][j][1]=0;acc[s][j][2]=0;acc[s][j][3]=0; }
        #pragma unroll
        for (int kt = 0; kt < 4; kt++){
            uint32_t ah[2][4], al[2][4];
            ldA(ah[0], Ah, mrow,      kt*16, lane);
            ldA(ah[1], Ah, mrow + 16, kt*16, lane);
            ldA(al[0], Al, mrow,      kt*16, lane);
            ldA(al[1], Al, mrow + 16, kt*16, lane);
            #pragma unroll
            for (int j = 0; j < 4; j++){
                uint32_t bh[2], bl[2];
                ldB(bh, Bh, n0 + j*8, kt*16, lane);
                ldB(bl, Bl, n0 + j*8, kt*16, lane);
                #pragma unroll
                for (int s = 0; s < 2; s++){
                    mma_bf16(acc[s][j], ah[s], bh);
                    mma_bf16(acc[s][j], al[s], bh);
                    mma_bf16(acc[s][j], ah[s], bl);
                }
            }
        }
        __syncthreads();   // all mma reads of A done before next build

        #pragma unroll
        for (int j = 0; j < 4; j++){
            int col = p*64 + n0 + j*8 + t2;
            #pragma unroll
            for (int s = 0; s < 2; s++){
                int row0 = r0 + mrow + s*16 + g, row1 = row0 + 8;
                if (row0 < rows){ float2 v; v.x=acc[s][j][0]; v.y=acc[s][j][1]; *(float2*)(Y + (size_t)row0*192 + col) = v; }
                if (row1 < rows){ float2 v; v.x=acc[s][j][2]; v.y=acc[s][j][3]; *(float2*)(Y + (size_t)row1*192 + col) = v; }
            }
            stat_reduce(acc[0][j][0]+acc[0][j][2]+acc[1][j][0]+acc[1][j][2],
                        acc[0][j][1]+acc[0][j][3]+acc[1][j][1]+acc[1][j][3],
                        acc[0][j][0]*acc[0][j][0]+acc[0][j][2]*acc[0][j][2]+acc[1][j][0]*acc[1][j][0]+acc[1][j][2]*acc[1][j][2],
                        acc[0][j][1]*acc[0][j][1]+acc[0][j][3]*acc[0][j][3]+acc[1][j][1]*acc[1][j][1]+acc[1][j][3]*acc[1][j][3],
                        sSum, sSq, col, lane);
        }
    }
    __syncthreads();
    if (tid < 192){
        atomicAdd(statsOut + tid, sSum[tid]);
        atomicAdd(statsOut + 192 + tid, sSq[tid]);
    }
}

// ---------- final GEMM1 [256->128], B streamed per K-chunk (occ 2) ----------
__global__ void __launch_bounds__(256,2)
mm_final1(const float* __restrict__ S0, const float* __restrict__ S1,
          const float* __restrict__ S2, const float* __restrict__ S3,
          const float* __restrict__ W1, float* __restrict__ Yf,
          float* __restrict__ statsOut, int rows)
{
    extern __shared__ __align__(16) unsigned char sm[];
    float* sSum = (float*)(sm + 73728);
    float* sSq  = (float*)(sm + 74240);
    int tid = threadIdx.x, wid = tid>>5, lane = tid&31;
    int r0 = blockIdx.x*128;
    if (tid < 128){ sSum[tid]=0.f; sSq[tid]=0.f; }

    const float* Ss[4] = {S0,S1,S2,S3};
    int mrow = wid*16;
    int g = lane>>2, t2 = (lane&3)*2;
    float acc[16][4];
    #pragma unroll
    for (int j = 0; j < 16; j++){ acc[j][0]=0;acc[j][1]=0;acc[j][2]=0;acc[j][3]=0; }

    #pragma unroll 1
    for (int kc = 0; kc < 4; kc++){
        {
            int lr = tid >> 1, half = tid & 1;
            int gr = r0 + lr;
            bool ok = gr < rows;
            float4 z = make_float4(0,0,0,0);
            const float4* ps = (const float4*)(Ss[kc] + (size_t)gr*64);
            #pragma unroll
            for (int i = 0; i < 8; i++){
                int c = half*32 + i*4;
                float4 v = ok ? ps[c>>2] : z;
                st2(sm, sm+18432, lr, c,   leakyf(v.x), leakyf(v.y));
                st2(sm, sm+18432, lr, c+2, leakyf(v.z), leakyf(v.w));
            }
            for (int idx = tid; idx < 8192; idx += 256){
                int k = idx>>7, n = idx&127;
                __nv_bfloat16 h,l; wsplit(W1[(size_t)(kc*64+k)*128 + n], &h, &l);
                uint32_t off = (uint32_t)(n*AST + k)*2;
                *(__nv_bfloat16*)(sm + 36864 + off) = h;
                *(__nv_bfloat16*)(sm + 55296 + off) = l;
            }
        }
        __syncthreads();
        const unsigned char* Ah = sm;
        const unsigned char* Al = sm + 18432;
        const unsigned char* Bh = sm + 36864;
        const unsigned char* Bl = sm + 55296;
        #pragma unroll
        for (int kt = 0; kt < 4; kt++){
            uint32_t ah[4], al[4];
            ldA(ah, Ah, mrow, kt*16, lane);
            ldA(al, Al, mrow, kt*16, lane);
            #pragma unroll
            for (int j = 0; j < 16; j++){
                uint32_t bh[2], bl[2];
                ldB(bh, Bh, j*8, kt*16, lane);
                ldB(bl, Bl, j*8, kt*16, lane);
                mma_bf16(acc[j], ah, bh);
                mma_bf16(acc[j], al, bh);
                mma_bf16(acc[j], ah, bl);
            }
        }
        __syncthreads();
    }
    #pragma unroll
    for (int j = 0; j < 16; j++){
        int col = j*8 + t2;
        int row0 = r0 + mrow + g, row1 = row0 + 8;
        if (row0 < rows){ float2 v; v.x=acc[j][0]; v.y=acc[j][1]; *(float2*)(Yf + (size_t)row0*128 + col) = v; }
        if (row1 < rows){ float2 v; v.x=acc[j][2]; v.y=acc[j][3]; *(float2*)(Yf + (size_t)row1*128 + col) = v; }
        stat_reduce(acc[j][0]+acc[j][2], acc[j][1]+acc[j][3],
                    acc[j][0]*acc[j][0]+acc[j][2]*acc[j][2],
                    acc[j][1]*acc[j][1]+acc[j][3]*acc[j][3],
                    sSum, sSq, col, lane);
    }
    __syncthreads();
    if (tid < 128){
        atomicAdd(statsOut + tid, sSum[tid]);
        atomicAdd(statsOut + 192 + tid, sSq[tid]);
    }
}

// ---------- final GEMM2 [128->64] (occ 2) ----------
__global__ void __launch_bounds__(256,2)
mm_final2(const float* __restrict__ Yf, int w, const float* __restrict__ W2,
          float* __restrict__ outp, int rows)
{
    extern __shared__ __align__(16) unsigned char sm[];
    int tid = threadIdx.x, wid = tid>>5, lane = tid&31;
    int r0 = blockIdx.x*128;

    for (int idx = tid; idx < 8192; idx += 256){
        int cc = idx>>12, k = (idx>>6)&63, n = idx&63;
        __nv_bfloat16 h,l; wsplit(W2[(size_t)(cc*64+k)*64 + n], &h, &l);
        unsigned char* base = sm + 36864 + cc*18432;
        uint32_t off = (uint32_t)(n*AST + k)*2;
        *(__nv_bfloat16*)(base + off) = h;
        *(__nv_bfloat16*)(base + 9216 + off) = l;
    }

    int mrow = wid*16;
    int g = lane>>2, t2 = (lane&3)*2;
    float acc[8][4];
    #pragma unroll
    for (int j = 0; j < 8; j++){ acc[j][0]=0;acc[j][1]=0;acc[j][2]=0;acc[j][3]=0; }

    #pragma unroll 1
    for (int cc = 0; cc < 2; cc++){
        __syncthreads();
        {
            int lr = tid >> 1, half = tid & 1;
            int gr = r0 + lr;
            bool ok = gr < rows;
            float4 z = make_float4(0,0,0,0);
            const float4* py = (const float4*)(Yf + (size_t)gr*128);
            #pragma unroll
            for (int i = 0; i < 8; i++){
                int c = half*32 + i*4;
                int kg = cc*64 + c;
                float4 v = ok ? py[kg>>2] : z;
                float4 m  = *(const float4*)(&g_fmean[w][kg]);
                float4 iv = *(const float4*)(&g_finv[w][kg]);
                st2(sm, sm+18432, lr, c,   leakyf((v.x-m.x)*iv.x), leakyf((v.y-m.y)*iv.y));
                st2(sm, sm+18432, lr, c+2, leakyf((v.z-m.z)*iv.z), leakyf((v.w-m.w)*iv.w));
            }
        }
        __syncthreads();
        const unsigned char* Ah = sm;
        const unsigned char* Al = sm + 18432;
        const unsigned char* Bh = sm + 36864 + cc*18432;
        const unsigned char* Bl = Bh + 9216;
        #pragma unroll
        for (int kt = 0; kt < 4; kt++){
            uint32_t ah[4], al[4];
            ldA(ah, Ah, mrow, kt*16, lane);
            ldA(al, Al, mrow, kt*16, lane);
            #pragma unroll
            for (int j = 0; j < 8; j++){
                uint32_t bh[2], bl[2];
                ldB(bh, Bh, j*8, kt*16, lane);
                ldB(bl, Bl, j*8, kt*16, lane);
                mma_bf16(acc[j], ah, bh);
                mma_bf16(acc[j], al, bh);
                mma_bf16(acc[j], ah, bl);
            }
        }
    }
    #pragma unroll
    for (int j = 0; j < 8; j++){
        int col = j*8 + t2;
        int row0 = r0 + mrow + g, row1 = row0 + 8;
        if (row0 < rows){ float2 v; v.x=acc[j][0]; v.y=acc[j][1]; *(float2*)(outp + (size_t)row0*64 + col) = v; }
        if (row1 < rows){ float2 v; v.x=acc[j][2]; v.y=acc[j][3]; *(float2*)(outp + (size_t)row1*64 + col) = v; }
    }
}

// ---------- BN finalize / normalize ----------
__global__ void k_finalize(int linkBase, float rowsInv){
    int link = linkBase + blockIdx.x;
    int c = threadIdx.x;
    float m = g_stats[link][0][c]*rowsInv;
    float var = g_stats[link][1][c]*rowsInv - m*m;
    float inv = rsqrtf(var + EPS);
    float sc = g_softp[link][c>>6]*inv;
    g_scale[link][c] = sc;
    g_shift[link][c] = -m*sc;
}

__global__ void __launch_bounds__(256)
k_norm2(const float* __restrict__ YA, int lA,
        const float* __restrict__ YB, int lB,
        float* __restrict__ out, int rows)
{
    __shared__ float sc[2][192], sh[2][192];
    int tid = threadIdx.x;
    for (int i = tid; i < 192; i += 256){
        sc[0][i]=g_scale[lA][i]; sh[0][i]=g_shift[lA][i];
        sc[1][i]=g_scale[lB][i]; sh[1][i]=g_shift[lB][i];
    }
    __syncthreads();
    long idx = (long)blockIdx.x*blockDim.x + tid;
    if (idx >= (long)rows*16) return;
    long row = idx >> 4;
    int d = (int)(idx & 15)*4;
    const float4* a = (const float4*)(YA + row*192);
    const float4* b = (const float4*)(YB + row*192);
    float4 o = make_float4(0,0,0,0);
    #pragma unroll
    for (int i = 0; i < 3; i++){
        int c = i*64 + d;
        float4 ya = a[c>>2], yb = b[c>>2];
        o.x += ya.x*sc[0][c+0]+sh[0][c+0] + yb.x*sc[1][c+0]+sh[1][c+0];
        o.y += ya.y*sc[0][c+1]+sh[0][c+1] + yb.y*sc[1][c+1]+sh[1][c+1];
        o.z += ya.z*sc[0][c+2]+sh[0][c+2] + yb.z*sc[1][c+2]+sh[1][c+2];
        o.w += ya.w*sc[0][c+3]+sh[0][c+3] + yb.w*sc[1][c+3]+sh[1][c+3];
    }
    *(float4*)(out + row*64 + d) = o;
}

__global__ void k_finalizeF(int idx, float rowsInv, int w){
    int c = threadIdx.x;
    const float* st = &g_stats[idx][0][0];
    float m = st[c]*rowsInv;
    float var = st[192+c]*rowsInv - m*m;
    g_fmean[w][c] = m;
    g_finv[w][c] = rsqrtf(var + EPS);
}

// ---------- host ----------
extern "C" void kernel_launch(void* const* d_in, const int* in_sizes, int n_in,
                              void* d_out, int out_size) {
    (void)in_sizes; (void)n_in; (void)out_size;
    const float* V0 = (const float*)d_in[0];
    const float* V1 = (const float*)d_in[1];
    const float* E0 = (const float*)d_in[2];
    const float* E1 = (const float*)d_in[3];
    const int*  src = (const int*)d_in[4];
    const int*  dst = (const int*)d_in[5];
    const float* arch = (const float*)d_in[6];
    const float* Wv  = (const float*)d_in[7];
    const float* We  = (const float*)d_in[8];
    const float* Wv1 = (const float*)d_in[9];
    const float* Wv2 = (const float*)d_in[10];
    const float* We1 = (const float*)d_in[11];
    const float* We2 = (const float*)d_in[12];
    float* outV = (float*)d_out;
    float* outE = outV + (size_t)NN*64;

    const int SM_G3 = 93696, SM_F1 = 74752, SM_F2 = 73728;
    cudaFuncSetAttribute(mm_gemm3<true>,  cudaFuncAttributeMaxDynamicSharedMemorySize, SM_G3);
    cudaFuncSetAttribute(mm_gemm3<false>, cudaFuncAttributeMaxDynamicSharedMemorySize, SM_G3);
    cudaFuncSetAttribute(mm_final1, cudaFuncAttributeMaxDynamicSharedMemorySize, SM_F1);
    cudaFuncSetAttribute(mm_final2, cudaFuncAttributeMaxDynamicSharedMemorySize, SM_F2);

    float *YvA,*YvB,*YeA,*YeB,*V2,*V3,*E2,*E3,*aSA,*aMA,*aSB,*aMB,*Yfv,*Yfe,*stats;
    cudaGetSymbolAddress((void**)&YvA, g_YvA);
    cudaGetSymbolAddress((void**)&YvB, g_YvB);
    cudaGetSymbolAddress((void**)&YeA, g_YeA);
    cudaGetSymbolAddress((void**)&YeB, g_YeB);
    cudaGetSymbolAddress((void**)&V2,  g_V2);
    cudaGetSymbolAddress((void**)&V3,  g_V3);
    cudaGetSymbolAddress((void**)&E2,  g_E2);
    cudaGetSymbolAddress((void**)&E3,  g_E3);
    cudaGetSymbolAddress((void**)&aSA, g_aggSA);
    cudaGetSymbolAddress((void**)&aMA, g_aggMA);
    cudaGetSymbolAddress((void**)&aSB, g_aggSB);
    cudaGetSymbolAddress((void**)&aMB, g_aggMB);
    cudaGetSymbolAddress((void**)&Yfv, g_Yfv);
    cudaGetSymbolAddress((void**)&Yfe, g_Yfe);
    cudaGetSymbolAddress((void**)&stats, g_stats);
    #define STATS(i) (stats + (size_t)(i)*384)

    const int NBN = (NN + 127)/128, NBE = NE/128;
    const float invN = 1.f/NN, invE = 1.f/NE;

    k_prep<<<196,256>>>(arch);
    k_count<<<(NE+255)/256,256>>>(dst);
    mm_gemm3<true><<<NBE,256,SM_G3>>>(E0, V0, nullptr, src, dst, We + 0*12288, YeA, STATS(4), NE);
    mm_gemm3<true><<<NBE,256,SM_G3>>>(E1, V1, nullptr, src, dst, We + 1*12288, YeB, STATS(5), NE);
    k_finalize<<<2,192>>>(4, invE);
    k_norm2<<<(NE*16+255)/256,256>>>(YeA, 4, YeB, 5, E2, NE);

    k_scan<<<1,1024>>>();
    k_scatter<<<(NE+255)/256,256>>>(src,dst);
    k_agg<<<(NN*32+255)/256,256>>>(E0, V0, aSA, aMA);
    k_agg<<<(NN*32+255)/256,256>>>(E1, V1, aSB, aMB);

    mm_gemm3<false><<<NBN,256,SM_G3>>>(V0, aSA, aMA, nullptr, nullptr, Wv + 0*12288, YvA, STATS(0), NN);
    mm_gemm3<false><<<NBN,256,SM_G3>>>(V1, aSB, aMB, nullptr, nullptr, Wv + 1*12288, YvB, STATS(1), NN);
    k_finalize<<<2,192>>>(0, invN);
    k_norm2<<<(NN*16+255)/256,256>>>(YvA, 0, YvB, 1, V2, NN);

    k_agg<<<(NN*32+255)/256,256>>>(E2, V2, aSA, aMA);

    mm_gemm3<false><<<NBN,256,SM_G3>>>(V1, aSB, aMB, nullptr, nullptr, Wv + 2*12288, YvA, STATS(2), NN);
    mm_gemm3<false><<<NBN,256,SM_G3>>>(V2, aSA, aMA, nullptr, nullptr, Wv + 3*12288, YvB, STATS(3), NN);
    k_finalize<<<2,192>>>(2, invN);
    k_norm2<<<(NN*16+255)/256,256>>>(YvA, 2, YvB, 3, V3, NN);

    mm_gemm3<true><<<NBE,256,SM_G3>>>(E1, V1, nullptr, src, dst, We + 2*12288, YeA, STATS(6), NE);
    mm_gemm3<true><<<NBE,256,SM_G3>>>(E2, V2, nullptr, src, dst, We + 3*12288, YeB, STATS(7), NE);
    k_finalize<<<2,192>>>(6, invE);
    k_norm2<<<(NE*16+255)/256,256>>>(YeA, 6, YeB, 7, E3, NE);

    mm_final1<<<NBN,256,SM_F1>>>(V0, V1, V2, V3, Wv1, Yfv, STATS(8), NN);
    k_finalizeF<<<1,128>>>(8, invN, 0);
    mm_final2<<<NBN,256,SM_F2>>>(Yfv, 0, Wv2, outV, NN);

    mm_final1<<<NBE,256,SM_F1>>>(E0, E1, E2, E3, We1, Yfe, STATS(9), NE);
    k_finalizeF<<<1,128>>>(9, invE, 1);
    mm_final2<<<NBE,256,SM_F2>>>(Yfe, 1, We2, outE, NE);
    #undef STATS
}

// round 17
// speedup vs baseline: 1.6272x; 1.0241x over previous
#include <cuda_runtime.h>
#include <cuda_bf16.h>
#include <math.h>
#include <stdint.h>

#define NN 50000
#define NE 800000
#define EPS 1e-5f
#define AST 72

// ---------- static scratch ----------
__device__ __align__(16) float g_V2[NN*64];
__device__ __align__(16) float g_V3[NN*64];
__device__ __align__(16) float g_aggSA[NN*64];
__device__ __align__(16) float g_aggMA[NN*64];
__device__ __align__(16) float g_aggSB[NN*64];
__device__ __align__(16) float g_aggMB[NN*64];
__device__ __align__(16) float g_YvA[(size_t)NN*192];
__device__ __align__(16) float g_YvB[(size_t)NN*192];
__device__ __align__(16) float g_E2[(size_t)NE*64];
__device__ __align__(16) float g_E3[(size_t)NE*64];
__device__ __align__(16) float g_YeA[(size_t)NE*192];
__device__ __align__(16) float g_YeB[(size_t)NE*192];
__device__ __align__(16) float g_Yfv[(size_t)NN*128];
__device__ __align__(16) float g_Yfe[(size_t)NE*128];
__device__ int   g_deg[NN];
__device__ int   g_rowptr[NN+1];
__device__ int   g_cursor[NN];
__device__ int   g_perm[NE];
__device__ int   g_srcPerm[NE];
__device__ __align__(16) float g_softp[8][3];
__device__ __align__(16) float g_stats[10][2][192];
__device__ __align__(16) float g_scale[8][192];
__device__ __align__(16) float g_shift[8][192];
__device__ __align__(16) float g_fmean[2][128];
__device__ __align__(16) float g_finv[2][128];

__device__ __forceinline__ float leakyf(float x){ return x > 0.f ? x : 0.2f*x; }

// ---------- mma.sync helpers ----------
static __device__ __forceinline__ void mma_bf16(float* d, const uint32_t* a, const uint32_t* b){
    asm volatile("mma.sync.aligned.m16n8k16.row.col.f32.bf16.bf16.f32 "
        "{%0,%1,%2,%3}, {%4,%5,%6,%7}, {%8,%9}, {%0,%1,%2,%3};"
        : "+f"(d[0]),"+f"(d[1]),"+f"(d[2]),"+f"(d[3])
        : "r"(a[0]),"r"(a[1]),"r"(a[2]),"r"(a[3]),"r"(b[0]),"r"(b[1]));
}
static __device__ __forceinline__ void ldA(uint32_t* a, const unsigned char* base, int mrow, int k0, int lane){
    int g = lane>>2, t2 = (lane&3)*2;
    const unsigned char* p = base + (size_t)((mrow+g)*AST + k0 + t2)*2;
    a[0] = *(const uint32_t*)p;
    a[2] = *(const uint32_t*)(p + 16);
    const unsigned char* q = p + 8*AST*2;
    a[1] = *(const uint32_t*)q;
    a[3] = *(const uint32_t*)(q + 16);
}
static __device__ __forceinline__ void ldB(uint32_t* b, const unsigned char* base, int n0, int k0, int lane){
    int g = lane>>2, t2 = (lane&3)*2;
    const unsigned char* p = base + (size_t)((n0+g)*AST + k0 + t2)*2;
    b[0] = *(const uint32_t*)p;
    b[1] = *(const uint32_t*)(p + 16);
}
static __device__ __forceinline__ void st2(unsigned char* H, unsigned char* L, int row, int col, float v0, float v1){
    uint32_t off = (uint32_t)(row*AST + col)*2;
    __nv_bfloat16 h0=__float2bfloat16(v0), h1=__float2bfloat16(v1);
    __nv_bfloat16 l0=__float2bfloat16(v0-__bfloat162float(h0));
    __nv_bfloat16 l1=__float2bfloat16(v1-__bfloat162float(h1));
    __nv_bfloat162 th; th.x=h0; th.y=h1;
    __nv_bfloat162 tl; tl.x=l0; tl.y=l1;
    *(__nv_bfloat162*)(H+off)=th;
    *(__nv_bfloat162*)(L+off)=tl;
}
static __device__ __forceinline__ void wsplit(float w, __nv_bfloat16* h, __nv_bfloat16* l){
    *h = __float2bfloat16(w);
    *l = __float2bfloat16(w - __bfloat162float(*h));
}

// ---------- setup ----------
__global__ void k_prep(const float* __restrict__ arch){
    int idx = blockIdx.x*blockDim.x + threadIdx.x;
    if (idx < NN) g_deg[idx] = 0;
    if (idx < 10*2*192) (&g_stats[0][0][0])[idx] = 0.f;
    if (idx < 8){
        float a0=arch[idx*3+0], a1=arch[idx*3+1], a2=arch[idx*3+2];
        float mx=fmaxf(a0,fmaxf(a1,a2));
        float e0=__expf(a0-mx), e1=__expf(a1-mx), e2=__expf(a2-mx);
        float s=e0+e1+e2;
        g_softp[idx][0]=e0/s; g_softp[idx][1]=e1/s; g_softp[idx][2]=e2/s;
    }
}
__global__ void k_count(const int* __restrict__ dst){
    int e = blockIdx.x*blockDim.x + threadIdx.x;
    if (e < NE) atomicAdd(&g_deg[dst[e]], 1);
}
__global__ void k_scan(){
    __shared__ int part[1024];
    int tid = threadIdx.x;
    const int CH = (NN + 1023)/1024;
    int base = tid*CH, s = 0;
    for (int i = 0; i < CH; i++){ int ix = base+i; if (ix < NN) s += g_deg[ix]; }
    part[tid] = s; __syncthreads();
    for (int off = 1; off < 1024; off <<= 1){
        int v = part[tid];
        int add = (tid >= off) ? part[tid-off] : 0;
        __syncthreads(); part[tid] = v + add; __syncthreads();
    }
    int run = (tid == 0) ? 0 : part[tid-1];
    for (int i = 0; i < CH; i++){
        int ix = base+i;
        if (ix < NN){ g_rowptr[ix]=run; g_cursor[ix]=run; run += g_deg[ix]; }
    }
    if (tid == 1023) g_rowptr[NN] = part[1023];
}
__global__ void k_scatter(const int* __restrict__ src, const int* __restrict__ dst){
    int e = blockIdx.x*blockDim.x + threadIdx.x;
    if (e < NE){
        int d = dst[e];
        int pos = atomicAdd(&g_cursor[d], 1);
        g_perm[pos] = e;
        g_srcPerm[pos] = src[e];
    }
}

// ---------- aggregation ----------
__global__ void __launch_bounds__(256)
k_agg(const float* __restrict__ Es, const float* __restrict__ V,
      float* __restrict__ aggS, float* __restrict__ aggM)
{
    int warp = (blockIdx.x*blockDim.x + threadIdx.x) >> 5;
    int lane = threadIdx.x & 31;
    if (warp >= NN) return;
    int beg = g_rowptr[warp], end = g_rowptr[warp+1];
    float s0=0.f, s1=0.f, m0=-INFINITY, m1=-INFINITY;
    for (int i = beg; i < end; i++){
        int e = g_perm[i], s = g_srcPerm[i];
        float2 ev = *reinterpret_cast<const float2*>(Es + (size_t)e*64 + lane*2);
        float2 vv = *reinterpret_cast<const float2*>(V  + (size_t)s*64 + lane*2);
        float g0 = __fdividef(1.f, 1.f + __expf(-ev.x));
        float g1 = __fdividef(1.f, 1.f + __expf(-ev.y));
        float a = vv.x*g0, b = vv.y*g1;
        s0 += a; s1 += b; m0 = fmaxf(m0,a); m1 = fmaxf(m1,b);
    }
    if (beg == end){ m0 = 0.f; m1 = 0.f; }
    size_t o = (size_t)warp*64 + lane*2;
    aggS[o]=s0; aggS[o+1]=s1; aggM[o]=m0; aggM[o+1]=m1;
}

// ---------- stats reduce ----------
static __device__ __forceinline__ void stat_reduce(float s0, float s1, float q0, float q1,
                                                   float* sSum, float* sSq, int col, int lane){
    #pragma unroll
    for (int off = 4; off < 32; off <<= 1){
        s0 += __shfl_xor_sync(0xFFFFFFFFu, s0, off);
        s1 += __shfl_xor_sync(0xFFFFFFFFu, s1, off);
        q0 += __shfl_xor_sync(0xFFFFFFFFu, q0, off);
        q1 += __shfl_xor_sync(0xFFFFFFFFu, q1, off);
    }
    if (lane < 4){
        atomicAdd(&sSum[col],   s0);
        atomicAdd(&sSum[col+1], s1);
        atomicAdd(&sSq[col],    q0);
        atomicAdd(&sSq[col+1],  q1);
    }
}

// ---------- 3-candidate mixed GEMM, candidate-streamed (occ 2), M32xN32 warp tiles ----------
// Build: row-per-warp mapping, lane covers cols 2l..2l+1 -> conflict-free STS.
// smem: A hi@0 lo@18432 (36864); B cand p: hi@36864+p*18432, lo=+9216 (end 92160)
//       sSum@92160 (192f), sSq@92928 -> 93696 total
template<bool EDGE>
__global__ void __launch_bounds__(256,2)
mm_gemm3(const float* __restrict__ A0, const float* __restrict__ A1,
         const float* __restrict__ A2,
         const int* __restrict__ srcI, const int* __restrict__ dstI,
         const float* __restrict__ W, float* __restrict__ Y,
         float* __restrict__ statsOut, int rows)
{
    extern __shared__ __align__(16) unsigned char sm[];
    float* sSum = (float*)(sm + 92160);
    float* sSq  = (float*)(sm + 92928);
    int tid = threadIdx.x, wid = tid>>5, lane = tid&31;
    int r0 = blockIdx.x*128;
    if (tid < 192){ sSum[tid]=0.f; sSq[tid]=0.f; }

    for (int idx = tid; idx < 12288; idx += 256){
        int p = idx>>12, k = (idx>>6)&63, n = idx&63;
        __nv_bfloat16 h,l; wsplit(W[p*4096 + k*64 + n], &h, &l);
        unsigned char* base = sm + 36864 + p*18432;
        uint32_t off = (uint32_t)(n*AST + k)*2;
        *(__nv_bfloat16*)(base + off) = h;
        *(__nv_bfloat16*)(base + 9216 + off) = l;
    }

    int mrow = (wid & 3)*32;
    int n0   = (wid >> 2)*32;
    int g = lane>>2, t2 = (lane&3)*2;
    int bcol = lane*2;   // build column pair for this lane

    #pragma unroll 1
    for (int p = 0; p < 3; p++){
        // build candidate p: warp wid fills rows wid*16 .. wid*16+15, lane covers cols 2l,2l+1
        {
            float2 z2 = make_float2(0.f,0.f);
            unsigned char* H = sm; unsigned char* L = sm + 18432;
            #pragma unroll 4
            for (int it = 0; it < 16; it++){
                int row = wid*16 + it;
                int gr2 = r0 + row;
                bool ok2 = gr2 < rows;
                float2 v;
                if (EDGE){
                    if (p == 0){
                        v = ok2 ? *(const float2*)(A0 + (size_t)gr2*64 + bcol) : z2;
                    } else {
                        int s = ok2 ? srcI[gr2] : 0;
                        int d = ok2 ? dstI[gr2] : 0;
                        float2 a = ok2 ? *(const float2*)(A1 + (size_t)s*64 + bcol) : z2;
                        float2 b = ok2 ? *(const float2*)(A1 + (size_t)d*64 + bcol) : z2;
                        if (p == 1){
                            float2 e = ok2 ? *(const float2*)(A0 + (size_t)gr2*64 + bcol) : z2;
                            v.x = e.x + a.x + b.x; v.y = e.y + a.y + b.y;
                        } else {
                            v.x = a.x*b.x; v.y = a.y*b.y;
                        }
                    }
                } else {
                    const float* Ap = (p==0) ? A0 : (p==1) ? A1 : A2;
                    v = ok2 ? *(const float2*)(Ap + (size_t)gr2*64 + bcol) : z2;
                }
                st2(H, L, row, bcol, v.x, v.y);
            }
        }
        __syncthreads();

        const unsigned char* Ah = sm;
        const unsigned char* Al = sm + 18432;
        const unsigned char* Bh = sm + 36864 + p*18432;
        const unsigned char* Bl = Bh + 9216;
        float acc[2][4][4];
        #pragma unroll
        for (int s = 0; s < 2; s++)
            #pragma unroll
            for (int j = 0; j < 4; j++){ acc[s][j][0]=0;acc[s][j][1]=0;acc[s][j][2]=0;acc[s][j][3]=0; }
        #pragma unroll
        for (int kt = 0; kt < 4; kt++){
            uint32_t ah[2][4], al[2][4];
            ldA(ah[0], Ah, mrow,      kt*16, lane);
            ldA(ah[1], Ah, mrow + 16, kt*16, lane);
            ldA(al[0], Al, mrow,      kt*16, lane);
            ldA(al[1], Al, mrow + 16, kt*16, lane);
            #pragma unroll
            for (int j = 0; j < 4; j++){
                uint32_t bh[2], bl[2];
                ldB(bh, Bh, n0 + j*8, kt*16, lane);
                ldB(bl, Bl, n0 + j*8, kt*16, lane);
                #pragma unroll
                for (int s = 0; s < 2; s++){
                    mma_bf16(acc[s][j], ah[s], bh);
                    mma_bf16(acc[s][j], al[s], bh);
                    mma_bf16(acc[s][j], ah[s], bl);
                }
            }
        }
        __syncthreads();

        #pragma unroll
        for (int j = 0; j < 4; j++){
            int col = p*64 + n0 + j*8 + t2;
            #pragma unroll
            for (int s = 0; s < 2; s++){
                int row0 = r0 + mrow + s*16 + g, row1 = row0 + 8;
                if (row0 < rows){ float2 v; v.x=acc[s][j][0]; v.y=acc[s][j][1]; *(float2*)(Y + (size_t)row0*192 + col) = v; }
                if (row1 < rows){ float2 v; v.x=acc[s][j][2]; v.y=acc[s][j][3]; *(float2*)(Y + (size_t)row1*192 + col) = v; }
            }
            stat_reduce(acc[0][j][0]+acc[0][j][2]+acc[1][j][0]+acc[1][j][2],
                        acc[0][j][1]+acc[0][j][3]+acc[1][j][1]+acc[1][j][3],
                        acc[0][j][0]*acc[0][j][0]+acc[0][j][2]*acc[0][j][2]+acc[1][j][0]*acc[1][j][0]+acc[1][j][2]*acc[1][j][2],
                        acc[0][j][1]*acc[0][j][1]+acc[0][j][3]*acc[0][j][3]+acc[1][j][1]*acc[1][j][1]+acc[1][j][3]*acc[1][j][3],
                        sSum, sSq, col, lane);
        }
    }
    __syncthreads();
    if (tid < 192){
        atomicAdd(statsOut + tid, sSum[tid]);
        atomicAdd(statsOut + 192 + tid, sSq[tid]);
    }
}

// ---------- final GEMM1 [256->128], B streamed per K-chunk (occ 2), M32xN64 tiles ----------
__global__ void __launch_bounds__(256,2)
mm_final1(const float* __restrict__ S0, const float* __restrict__ S1,
          const float* __restrict__ S2, const float* __restrict__ S3,
          const float* __restrict__ W1, float* __restrict__ Yf,
          float* __restrict__ statsOut, int rows)
{
    extern __shared__ __align__(16) unsigned char sm[];
    float* sSum = (float*)(sm + 73728);
    float* sSq  = (float*)(sm + 74240);
    int tid = threadIdx.x, wid = tid>>5, lane = tid&31;
    int r0 = blockIdx.x*128;
    if (tid < 128){ sSum[tid]=0.f; sSq[tid]=0.f; }

    const float* Ss[4] = {S0,S1,S2,S3};
    int mrow = (wid & 3)*32;
    int n0   = (wid >> 2)*64;
    int g = lane>>2, t2 = (lane&3)*2;
    float acc[2][8][4];
    #pragma unroll
    for (int s = 0; s < 2; s++)
        #pragma unroll
        for (int j = 0; j < 8; j++){ acc[s][j][0]=0;acc[s][j][1]=0;acc[s][j][2]=0;acc[s][j][3]=0; }

    #pragma unroll 1
    for (int kc = 0; kc < 4; kc++){
        {
            int lr = tid >> 1, half = tid & 1;
            int gr = r0 + lr;
            bool ok = gr < rows;
            float4 z = make_float4(0,0,0,0);
            const float4* ps = (const float4*)(Ss[kc] + (size_t)gr*64);
            #pragma unroll
            for (int i = 0; i < 8; i++){
                int c = half*32 + i*4;
                float4 v = ok ? ps[c>>2] : z;
                st2(sm, sm+18432, lr, c,   leakyf(v.x), leakyf(v.y));
                st2(sm, sm+18432, lr, c+2, leakyf(v.z), leakyf(v.w));
            }
            for (int idx = tid; idx < 8192; idx += 256){
                int k = idx>>7, n = idx&127;
                __nv_bfloat16 h,l; wsplit(W1[(size_t)(kc*64+k)*128 + n], &h, &l);
                uint32_t off = (uint32_t)(n*AST + k)*2;
                *(__nv_bfloat16*)(sm + 36864 + off) = h;
                *(__nv_bfloat16*)(sm + 55296 + off) = l;
            }
        }
        __syncthreads();
        const unsigned char* Ah = sm;
        const unsigned char* Al = sm + 18432;
        const unsigned char* Bh = sm + 36864;
        const unsigned char* Bl = sm + 55296;
        #pragma unroll
        for (int kt = 0; kt < 4; kt++){
            uint32_t ah[2][4], al[2][4];
            ldA(ah[0], Ah, mrow,      kt*16, lane);
            ldA(ah[1], Ah, mrow + 16, kt*16, lane);
            ldA(al[0], Al, mrow,      kt*16, lane);
            ldA(al[1], Al, mrow + 16, kt*16, lane);
            #pragma unroll
            for (int j = 0; j < 8; j++){
                uint32_t bh[2], bl[2];
                ldB(bh, Bh, n0 + j*8, kt*16, lane);
                ldB(bl, Bl, n0 + j*8, kt*16, lane);
                #pragma unroll
                for (int s = 0; s < 2; s++){
                    mma_bf16(acc[s][j], ah[s], bh);
                    mma_bf16(acc[s][j], al[s], bh);
                    mma_bf16(acc[s][j], ah[s], bl);
                }
            }
        }
        __syncthreads();
    }
    #pragma unroll
    for (int j = 0; j < 8; j++){
        int col = n0 + j*8 + t2;
        #pragma unroll
        for (int s = 0; s < 2; s++){
            int row0 = r0 + mrow + s*16 + g, row1 = row0 + 8;
            if (row0 < rows){ float2 v; v.x=acc[s][j][0]; v.y=acc[s][j][1]; *(float2*)(Yf + (size_t)row0*128 + col) = v; }
            if (row1 < rows){ float2 v; v.x=acc[s][j][2]; v.y=acc[s][j][3]; *(float2*)(Yf + (size_t)row1*128 + col) = v; }
        }
        stat_reduce(acc[0][j][0]+acc[0][j][2]+acc[1][j][0]+acc[1][j][2],
                    acc[0][j][1]+acc[0][j][3]+acc[1][j][1]+acc[1][j][3],
                    acc[0][j][0]*acc[0][j][0]+acc[0][j][2]*acc[0][j][2]+acc[1][j][0]*acc[1][j][0]+acc[1][j][2]*acc[1][j][2],
                    acc[0][j][1]*acc[0][j][1]+acc[0][j][3]*acc[0][j][3]+acc[1][j][1]*acc[1][j][1]+acc[1][j][3]*acc[1][j][3],
                    sSum, sSq, col, lane);
    }
    __syncthreads();
    if (tid < 128){
        atomicAdd(statsOut + tid, sSum[tid]);
        atomicAdd(statsOut + 192 + tid, sSq[tid]);
    }
}

// ---------- final GEMM2 [128->64] (occ 2), M32xN32 tiles ----------
__global__ void __launch_bounds__(256,2)
mm_final2(const float* __restrict__ Yf, int w, const float* __restrict__ W2,
          float* __restrict__ outp, int rows)
{
    extern __shared__ __align__(16) unsigned char sm[];
    int tid = threadIdx.x, wid = tid>>5, lane = tid&31;
    int r0 = blockIdx.x*128;

    for (int idx = tid; idx < 8192; idx += 256){
        int cc = idx>>12, k = (idx>>6)&63, n = idx&63;
        __nv_bfloat16 h,l; wsplit(W2[(size_t)(cc*64+k)*64 + n], &h, &l);
        unsigned char* base = sm + 36864 + cc*18432;
        uint32_t off = (uint32_t)(n*AST + k)*2;
        *(__nv_bfloat16*)(base + off) = h;
        *(__nv_bfloat16*)(base + 9216 + off) = l;
    }

    int mrow = (wid & 3)*32;
    int n0   = (wid >> 2)*32;
    int g = lane>>2, t2 = (lane&3)*2;
    float acc[2][4][4];
    #pragma unroll
    for (int s = 0; s < 2; s++)
        #pragma unroll
        for (int j = 0; j < 4; j++){ acc[s][j][0]=0;acc[s][j][1]=0;acc[s][j][2]=0;acc[s][j][3]=0; }

    #pragma unroll 1
    for (int cc = 0; cc < 2; cc++){
        __syncthreads();
        {
            int lr = tid >> 1, half = tid & 1;
            int gr = r0 + lr;
            bool ok = gr < rows;
            float4 z = make_float4(0,0,0,0);
            const float4* py = (const float4*)(Yf + (size_t)gr*128);
            #pragma unroll
            for (int i = 0; i < 8; i++){
                int c = half*32 + i*4;
                int kg = cc*64 + c;
                float4 v = ok ? py[kg>>2] : z;
                float4 m  = *(const float4*)(&g_fmean[w][kg]);
                float4 iv = *(const float4*)(&g_finv[w][kg]);
                st2(sm, sm+18432, lr, c,   leakyf((v.x-m.x)*iv.x), leakyf((v.y-m.y)*iv.y));
                st2(sm, sm+18432, lr, c+2, leakyf((v.z-m.z)*iv.z), leakyf((v.w-m.w)*iv.w));
            }
        }
        __syncthreads();
        const unsigned char* Ah = sm;
        const unsigned char* Al = sm + 18432;
        const unsigned char* Bh = sm + 36864 + cc*18432;
        const unsigned char* Bl = Bh + 9216;
        #pragma unroll
        for (int kt = 0; kt < 4; kt++){
            uint32_t ah[2][4], al[2][4];
            ldA(ah[0], Ah, mrow,      kt*16, lane);
            ldA(ah[1], Ah, mrow + 16, kt*16, lane);
            ldA(al[0], Al, mrow,      kt*16, lane);
            ldA(al[1], Al, mrow + 16, kt*16, lane);
            #pragma unroll
            for (int j = 0; j < 4; j++){
                uint32_t bh[2], bl[2];
                ldB(bh, Bh, n0 + j*8, kt*16, lane);
                ldB(bl, Bl, n0 + j*8, kt*16, lane);
                #pragma unroll
                for (int s = 0; s < 2; s++){
                    mma_bf16(acc[s][j], ah[s], bh);
                    mma_bf16(acc[s][j], al[s], bh);
                    mma_bf16(acc[s][j], ah[s], bl);
                }
            }
        }
    }
    #pragma unroll
    for (int j = 0; j < 4; j++){
        int col = n0 + j*8 + t2;
        #pragma unroll
        for (int s = 0; s < 2; s++){
            int row0 = r0 + mrow + s*16 + g, row1 = row0 + 8;
            if (row0 < rows){ float2 v; v.x=acc[s][j][0]; v.y=acc[s][j][1]; *(float2*)(outp + (size_t)row0*64 + col) = v; }
            if (row1 < rows){ float2 v; v.x=acc[s][j][2]; v.y=acc[s][j][3]; *(float2*)(outp + (size_t)row1*64 + col) = v; }
        }
    }
}

// ---------- BN finalize / normalize ----------
__global__ void k_finalize(int linkBase, float rowsInv){
    int link = linkBase + blockIdx.x;
    int c = threadIdx.x;
    float m = g_stats[link][0][c]*rowsInv;
    float var = g_stats[link][1][c]*rowsInv - m*m;
    float inv = rsqrtf(var + EPS);
    float sc = g_softp[link][c>>6]*inv;
    g_scale[link][c] = sc;
    g_shift[link][c] = -m*sc;
}

__global__ void __launch_bounds__(256)
k_norm2(const float* __restrict__ YA, int lA,
        const float* __restrict__ YB, int lB,
        float* __restrict__ out, int rows)
{
    __shared__ float sc[2][192], sh[2][192];
    int tid = threadIdx.x;
    for (int i = tid; i < 192; i += 256){
        sc[0][i]=g_scale[lA][i]; sh[0][i]=g_shift[lA][i];
        sc[1][i]=g_scale[lB][i]; sh[1][i]=g_shift[lB][i];
    }
    __syncthreads();
    long idx = (long)blockIdx.x*blockDim.x + tid;
    if (idx >= (long)rows*16) return;
    long row = idx >> 4;
    int d = (int)(idx & 15)*4;
    const float4* a = (const float4*)(YA + row*192);
    const float4* b = (const float4*)(YB + row*192);
    float4 o = make_float4(0,0,0,0);
    #pragma unroll
    for (int i = 0; i < 3; i++){
        int c = i*64 + d;
        float4 ya = a[c>>2], yb = b[c>>2];
        o.x += ya.x*sc[0][c+0]+sh[0][c+0] + yb.x*sc[1][c+0]+sh[1][c+0];
        o.y += ya.y*sc[0][c+1]+sh[0][c+1] + yb.y*sc[1][c+1]+sh[1][c+1];
        o.z += ya.z*sc[0][c+2]+sh[0][c+2] + yb.z*sc[1][c+2]+sh[1][c+2];
        o.w += ya.w*sc[0][c+3]+sh[0][c+3] + yb.w*sc[1][c+3]+sh[1][c+3];
    }
    *(float4*)(out + row*64 + d) = o;
}

__global__ void k_finalizeF(int idx, float rowsInv, int w){
    int c = threadIdx.x;
    const float* st = &g_stats[idx][0][0];
    float m = st[c]*rowsInv;
    float var = st[192+c]*rowsInv - m*m;
    g_fmean[w][c] = m;
    g_finv[w][c] = rsqrtf(var + EPS);
}

// ---------- host ----------
extern "C" void kernel_launch(void* const* d_in, const int* in_sizes, int n_in,
                              void* d_out, int out_size) {
    (void)in_sizes; (void)n_in; (void)out_size;
    const float* V0 = (const float*)d_in[0];
    const float* V1 = (const float*)d_in[1];
    const float* E0 = (const float*)d_in[2];
    const float* E1 = (const float*)d_in[3];
    const int*  src = (const int*)d_in[4];
    const int*  dst = (const int*)d_in[5];
    const float* arch = (const float*)d_in[6];
    const float* Wv  = (const float*)d_in[7];
    const float* We  = (const float*)d_in[8];
    const float* Wv1 = (const float*)d_in[9];
    const float* Wv2 = (const float*)d_in[10];
    const float* We1 = (const float*)d_in[11];
    const float* We2 = (const float*)d_in[12];
    float* outV = (float*)d_out;
    float* outE = outV + (size_t)NN*64;

    const int SM_G3 = 93696, SM_F1 = 74752, SM_F2 = 73728;
    cudaFuncSetAttribute(mm_gemm3<true>,  cudaFuncAttributeMaxDynamicSharedMemorySize, SM_G3);
    cudaFuncSetAttribute(mm_gemm3<false>, cudaFuncAttributeMaxDynamicSharedMemorySize, SM_G3);
    cudaFuncSetAttribute(mm_final1, cudaFuncAttributeMaxDynamicSharedMemorySize, SM_F1);
    cudaFuncSetAttribute(mm_final2, cudaFuncAttributeMaxDynamicSharedMemorySize, SM_F2);

    float *YvA,*YvB,*YeA,*YeB,*V2,*V3,*E2,*E3,*aSA,*aMA,*aSB,*aMB,*Yfv,*Yfe,*stats;
    cudaGetSymbolAddress((void**)&YvA, g_YvA);
    cudaGetSymbolAddress((void**)&YvB, g_YvB);
    cudaGetSymbolAddress((void**)&YeA, g_YeA);
    cudaGetSymbolAddress((void**)&YeB, g_YeB);
    cudaGetSymbolAddress((void**)&V2,  g_V2);
    cudaGetSymbolAddress((void**)&V3,  g_V3);
    cudaGetSymbolAddress((void**)&E2,  g_E2);
    cudaGetSymbolAddress((void**)&E3,  g_E3);
    cudaGetSymbolAddress((void**)&aSA, g_aggSA);
    cudaGetSymbolAddress((void**)&aMA, g_aggMA);
    cudaGetSymbolAddress((void**)&aSB, g_aggSB);
    cudaGetSymbolAddress((void**)&aMB, g_aggMB);
    cudaGetSymbolAddress((void**)&Yfv, g_Yfv);
    cudaGetSymbolAddress((void**)&Yfe, g_Yfe);
    cudaGetSymbolAddress((void**)&stats, g_stats);
    #define STATS(i) (stats + (size_t)(i)*384)

    const int NBN = (NN + 127)/128, NBE = NE/128;
    const float invN = 1.f/NN, invE = 1.f/NE;

    k_prep<<<196,256>>>(arch);
    k_count<<<(NE+255)/256,256>>>(dst);
    mm_gemm3<true><<<NBE,256,SM_G3>>>(E0, V0, nullptr, src, dst, We + 0*12288, YeA, STATS(4), NE);
    mm_gemm3<true><<<NBE,256,SM_G3>>>(E1, V1, nullptr, src, dst, We + 1*12288, YeB, STATS(5), NE);
    k_finalize<<<2,192>>>(4, invE);
    k_norm2<<<(NE*16+255)/256,256>>>(YeA, 4, YeB, 5, E2, NE);

    k_scan<<<1,1024>>>();
    k_scatter<<<(NE+255)/256,256>>>(src,dst);
    k_agg<<<(NN*32+255)/256,256>>>(E0, V0, aSA, aMA);
    k_agg<<<(NN*32+255)/256,256>>>(E1, V1, aSB, aMB);

    mm_gemm3<false><<<NBN,256,SM_G3>>>(V0, aSA, aMA, nullptr, nullptr, Wv + 0*12288, YvA, STATS(0), NN);
    mm_gemm3<false><<<NBN,256,SM_G3>>>(V1, aSB, aMB, nullptr, nullptr, Wv + 1*12288, YvB, STATS(1), NN);
    k_finalize<<<2,192>>>(0, invN);
    k_norm2<<<(NN*16+255)/256,256>>>(YvA, 0, YvB, 1, V2, NN);

    k_agg<<<(NN*32+255)/256,256>>>(E2, V2, aSA, aMA);

    mm_gemm3<false><<<NBN,256,SM_G3>>>(V1, aSB, aMB, nullptr, nullptr, Wv + 2*12288, YvA, STATS(2), NN);
    mm_gemm3<false><<<NBN,256,SM_G3>>>(V2, aSA, aMA, nullptr, nullptr, Wv + 3*12288, YvB, STATS(3), NN);
    k_finalize<<<2,192>>>(2, invN);
    k_norm2<<<(NN*16+255)/256,256>>>(YvA, 2, YvB, 3, V3, NN);

    mm_gemm3<true><<<NBE,256,SM_G3>>>(E1, V1, nullptr, src, dst, We + 2*12288, YeA, STATS(6), NE);
    mm_gemm3<true><<<NBE,256,SM_G3>>>(E2, V2, nullptr, src, dst, We + 3*12288, YeB, STATS(7), NE);
    k_finalize<<<2,192>>>(6, invE);
    k_norm2<<<(NE*16+255)/256,256>>>(YeA, 6, YeB, 7, E3, NE);

    mm_final1<<<NBN,256,SM_F1>>>(V0, V1, V2, V3, Wv1, Yfv, STATS(8), NN);
    k_finalizeF<<<1,128>>>(8, invN, 0);
    mm_final2<<<NBN,256,SM_F2>>>(Yfv, 0, Wv2, outV, NN);

    mm_final1<<<NBE,256,SM_F1>>>(E0, E1, E2, E3, We1, Yfe, STATS(9), NE);
    k_finalizeF<<<1,128>>>(9, invE, 1);
    mm_final2<<<NBE,256,SM_F2>>>(Yfe, 1, We2, outE, NE);
    #undef STATS
}